// round 14
// baseline (speedup 1.0000x reference)
#include <cuda_runtime.h>
#include <cuda_fp16.h>
#include <cuda_bf16.h>

#define NN 50000
#define EE 800000
#define HH 4

typedef unsigned long long ull;

// ---------------- scratch ----------------
__device__ __align__(16) __half g_xl1h[NN * 256];
__device__ __align__(16) __half g_xl2h[NN * 128];
__device__ __align__(16) float g_a1s[NN * 4];
__device__ __align__(16) float g_a1d[NN * 4];
__device__ __align__(16) float g_x2[NN * 64];
__device__ __align__(16) float g_a2s[NN * 4];
__device__ __align__(16) float g_a2d[NN * 4];
__device__ __align__(16) float g_ex2[EE * 4];
__device__ __align__(16) float g_den2[NN * 4];
__device__ __align__(16) __half g_pqh[NN * 128];
__device__ __align__(16) float g_wpq[32 * 128];
__device__ int  g_deg[NN];
__device__ int  g_ptr[NN];
__device__ int  g_pos[NN];
__device__ int  g_bsum[128];
__device__ __align__(8) int2 g_eid[EE];

__device__ __forceinline__ ull ffma2(ull a, ull b, ull c) {
    ull d;
    asm("fma.rn.f32x2 %0, %1, %2, %3;" : "=l"(d) : "l"(a), "l"(b), "l"(c));
    return d;
}
__device__ __forceinline__ ull add2(ull a, ull b) {
    ull d;
    asm("add.rn.f32x2 %0, %1, %2;" : "=l"(d) : "l"(a), "l"(b));
    return d;
}
__device__ __forceinline__ ull pack2(float x, float y) {
    ull d; asm("mov.b64 %0, {%1, %2};" : "=l"(d) : "f"(x), "f"(y)); return d;
}
__device__ __forceinline__ void unpack2(ull v, float& x, float& y) {
    asm("mov.b64 {%0, %1}, %2;" : "=f"(x), "=f"(y) : "l"(v));
}
__device__ __forceinline__ unsigned h2bits(float a, float b) {
    __half2 h = __floats2half2_rn(a, b);
    return *reinterpret_cast<unsigned*>(&h);
}
__device__ __forceinline__ float leaky_exp(float t) {
    t = fmaxf(t, 0.f) + 0.2f * fminf(t, 0.f);
    return __expf(t);
}
__device__ __forceinline__ unsigned tf32b(float f) {
    unsigned r; asm("cvt.rna.tf32.f32 %0, %1;" : "=r"(r) : "f"(f)); return r;
}

// ---------------- CSR build ----------------
__global__ void hist_kernel(const int* __restrict__ dst, int* __restrict__ deg) {
    int e = blockIdx.x * blockDim.x + threadIdx.x;
    if (e < EE) atomicAdd(&deg[dst[e]], 1);
}
__global__ void scanA_kernel(const int* __restrict__ deg, int* __restrict__ out,
                             int* __restrict__ bsum) {
    __shared__ int sm[512];
    int t = threadIdx.x;
    int g = blockIdx.x * 512 + t;
    int v = (g < NN) ? deg[g] : 0;
    sm[t] = v; __syncthreads();
    for (int o = 1; o < 512; o <<= 1) {
        int tt = (t >= o) ? sm[t - o] : 0;
        __syncthreads();
        sm[t] += tt;
        __syncthreads();
    }
    if (g < NN) out[g] = sm[t] - v;            // exclusive
    if (t == 511) bsum[blockIdx.x] = sm[511];
}
__global__ void scanB_kernel(int* __restrict__ bsum, int nb) {
    __shared__ int sm[128];
    int t = threadIdx.x;
    int v = (t < nb) ? bsum[t] : 0;
    sm[t] = v; __syncthreads();
    for (int o = 1; o < 128; o <<= 1) {
        int tt = (t >= o) ? sm[t - o] : 0;
        __syncthreads();
        sm[t] += tt;
        __syncthreads();
    }
    if (t < nb) bsum[t] = sm[t] - v;           // exclusive
}
__global__ void scanC_kernel(int* __restrict__ ptr, const int* __restrict__ bsum,
                             int* __restrict__ pos) {
    int g = blockIdx.x * 512 + threadIdx.x;
    if (g < NN) {
        int v = ptr[g] + bsum[blockIdx.x];
        ptr[g] = v;
        pos[g] = v;
    }
}
__global__ void scatter_kernel(const int* __restrict__ src, const int* __restrict__ dst,
                               int* __restrict__ pos, int2* __restrict__ eid) {
    int e = blockIdx.x * blockDim.x + threadIdx.x;
    if (e < EE) {
        int p = atomicAdd(&pos[dst[e]], 1);
        eid[p] = make_int2(e, src[e]);
    }
}

// -------- repack mW1 rows {0..31}->cols 0..63, rows {36..67}->cols 64..127 --------
__global__ void repack_wpq(const float* __restrict__ mW1, float* __restrict__ wpq) {
    int idx = blockIdx.x * blockDim.x + threadIdx.x;
    if (idx >= 32 * 128) return;
    int k = idx / 128, j = idx % 128;
    wpq[idx] = (j < 64) ? mW1[k * 64 + j] : mW1[(36 + k) * 64 + (j - 64)];
}

// ---------------- gemm1 via tf32 mma.sync (R10 config): Y[N,256] = X[N,128] @ W1[128,256] ----------------
#define SA 132
#define SB 264

#define LOAD_FRAGS(AF, BF, KC)                                              \
    do {                                                                    \
        int _kc = (KC);                                                     \
        _Pragma("unroll")                                                   \
        for (int mt = 0; mt < 4; mt++) {                                    \
            const float* ar = &Asm[(rwarp + mt * 16 + g) * SA + _kc];       \
            AF[mt][0] = __float_as_uint(ar[0]);                             \
            AF[mt][1] = __float_as_uint(ar[8 * SA]);                        \
            AF[mt][2] = __float_as_uint(ar[4]);                             \
            AF[mt][3] = __float_as_uint(ar[8 * SA + 4]);                    \
        }                                                                   \
        const float* br = &Bsm[(size_t)_kc * SB + cwarp + g];               \
        _Pragma("unroll")                                                   \
        for (int n8 = 0; n8 < 8; n8++) {                                    \
            BF[n8][0] = __float_as_uint(br[n8 * 8]);                        \
            BF[n8][1] = __float_as_uint(br[4 * SB + n8 * 8]);               \
        }                                                                   \
    } while (0)

#define MMA_FRAGS(AF, BF)                                                   \
    do {                                                                    \
        _Pragma("unroll")                                                   \
        for (int n8 = 0; n8 < 8; n8++)                                      \
            _Pragma("unroll")                                               \
            for (int mt = 0; mt < 4; mt++) {                                \
                asm volatile(                                               \
                    "mma.sync.aligned.m16n8k8.row.col.f32.tf32.tf32.f32 "  \
                    "{%0,%1,%2,%3}, {%4,%5,%6,%7}, {%8,%9}, {%0,%1,%2,%3};" \
                    : "+f"(acc[mt][n8][0]), "+f"(acc[mt][n8][1]),           \
                      "+f"(acc[mt][n8][2]), "+f"(acc[mt][n8][3])            \
                    : "r"(AF[mt][0]), "r"(AF[mt][1]),                       \
                      "r"(AF[mt][2]), "r"(AF[mt][3]),                       \
                      "r"(BF[n8][0]), "r"(BF[n8][1]));                      \
            }                                                               \
    } while (0)

__global__ __launch_bounds__(256, 1)
void gemm1_tf32(const float* __restrict__ X, const float* __restrict__ W,
                __half* __restrict__ Y,
                const float* __restrict__ att_s, const float* __restrict__ att_d,
                float* __restrict__ as_, float* __restrict__ ad_, int nN) {
    extern __shared__ float sm[];
    float* Asm = sm;                       // 128 x SA
    float* Bsm = sm + 128 * SA;            // 128 x SB
    float* satt = Bsm + 128 * SB;          // [0:256) att_s, [256:512) att_d
    const int tid = threadIdx.x;
    const int n0 = blockIdx.x * 128;
    const int nn = min(128, nN - n0);

    for (int i4 = tid; i4 < 128 * 32; i4 += 256) {
        int r = i4 >> 5, c4 = (i4 & 31) << 2;
        float4 v = (r < nn) ? *(const float4*)&X[(size_t)(n0 + r) * 128 + c4]
                            : make_float4(0.f, 0.f, 0.f, 0.f);
        uint4 u;
        u.x = tf32b(v.x); u.y = tf32b(v.y); u.z = tf32b(v.z); u.w = tf32b(v.w);
        *(uint4*)&Asm[r * SA + c4] = u;
    }
    for (int i4 = tid; i4 < 128 * 64; i4 += 256) {
        int k = i4 >> 6, c4 = (i4 & 63) << 2;
        float4 v = *(const float4*)&W[k * 256 + c4];
        uint4 u;
        u.x = tf32b(v.x); u.y = tf32b(v.y); u.z = tf32b(v.z); u.w = tf32b(v.w);
        *(uint4*)&Bsm[k * SB + c4] = u;
    }
    satt[tid] = att_s[tid];
    satt[256 + tid] = att_d[tid];
    __syncthreads();

    const int w = tid >> 5, lane = tid & 31;
    const int g = lane >> 2, t = lane & 3;
    const int wm = w & 1, wn = w >> 1;           // 2 x 4 warp grid
    const int rwarp = wm * 64;
    const int cwarp = wn * 64;

    float acc[4][8][4];
#pragma unroll
    for (int mt = 0; mt < 4; mt++)
#pragma unroll
        for (int n8 = 0; n8 < 8; n8++)
#pragma unroll
            for (int q = 0; q < 4; q++) acc[mt][n8][q] = 0.f;

    unsigned af0[4][4], bf0[8][2], af1[4][4], bf1[8][2];

    LOAD_FRAGS(af0, bf0, t);                       // k8 = 0
#pragma unroll 1
    for (int k8 = 0; k8 < 16; k8 += 2) {
        LOAD_FRAGS(af1, bf1, (k8 + 1) * 8 + t);
        MMA_FRAGS(af0, bf0);
        if (k8 + 2 < 16) LOAD_FRAGS(af0, bf0, (k8 + 2) * 8 + t);
        MMA_FRAGS(af1, bf1);
    }

#pragma unroll
    for (int mt = 0; mt < 4; mt++) {
        float ps0 = 0.f, pd0 = 0.f, ps1 = 0.f, pd1 = 0.f;
#pragma unroll
        for (int n8 = 0; n8 < 8; n8++) {
            int col = cwarp + n8 * 8 + 2 * t;
            float s0 = satt[col], s1 = satt[col + 1];
            float d0 = satt[256 + col], d1 = satt[256 + col + 1];
            ps0 += acc[mt][n8][0] * s0 + acc[mt][n8][1] * s1;
            pd0 += acc[mt][n8][0] * d0 + acc[mt][n8][1] * d1;
            ps1 += acc[mt][n8][2] * s0 + acc[mt][n8][3] * s1;
            pd1 += acc[mt][n8][2] * d0 + acc[mt][n8][3] * d1;
        }
#pragma unroll
        for (int o = 1; o <= 2; o <<= 1) {
            ps0 += __shfl_xor_sync(0xffffffffu, ps0, o);
            pd0 += __shfl_xor_sync(0xffffffffu, pd0, o);
            ps1 += __shfl_xor_sync(0xffffffffu, ps1, o);
            pd1 += __shfl_xor_sync(0xffffffffu, pd1, o);
        }
        int m0 = n0 + rwarp + mt * 16 + g;
        int m1 = m0 + 8;
        if (t == 0) {
            if (m0 < nN) { as_[(size_t)m0 * 4 + wn] = ps0; ad_[(size_t)m0 * 4 + wn] = pd0; }
            if (m1 < nN) { as_[(size_t)m1 * 4 + wn] = ps1; ad_[(size_t)m1 * 4 + wn] = pd1; }
        }
        bool w0 = (m0 < nN), w1 = (m1 < nN);
#pragma unroll
        for (int n8 = 0; n8 < 8; n8++) {
            int col = cwarp + n8 * 8 + 2 * t;
            if (w0) *(unsigned*)&Y[(size_t)m0 * 256 + col] = h2bits(acc[mt][n8][0], acc[mt][n8][1]);
            if (w1) *(unsigned*)&Y[(size_t)m1 * 256 + col] = h2bits(acc[mt][n8][2], acc[mt][n8][3]);
        }
    }
}

// ---------------- GEMM (FFMA2 path, used for layer2 + PQ): Y[N,M] = X[N,K] @ W[K,M] ----------------
template <int K, int M, int TN, int TH, int NSTEP, bool HALF_OUT, bool SC>
__launch_bounds__(TH, 1)
__global__ void gemm_xw(const float* __restrict__ X, const float* __restrict__ W,
                        void* __restrict__ Yv,
                        const float* __restrict__ att_s, const float* __restrict__ att_d,
                        float* __restrict__ as_, float* __restrict__ ad_, int nN) {
    extern __shared__ float sm[];
    constexpr int CG = M / 8;
    constexpr int PARTS = TH / CG;
    constexpr int NP = TN / PARTS;
    constexpr int HW = K * M / 2;
    static_assert(NP % NSTEP == 0, "NP % NSTEP");
    float* Xs = sm + K * M;
    const int tid = threadIdx.x;

    for (int i4 = tid; i4 < K * M / 4; i4 += TH) {
        int i = i4 * 4;
        int k = i / M, c = i % M;
        float4 v = *(const float4*)&W[i];
        int grp = (c >> 2) & 1;
        int d = (k * (M / 8) + (c >> 3)) * 4;
        *(float4*)&sm[(grp ? HW : 0) + d] = v;
    }
    const int n0 = blockIdx.x * TN;
    const int nn = min(TN, nN - n0);
    for (int i4 = tid; i4 < nn * K / 4; i4 += TH)
        ((float4*)Xs)[i4] = ((const float4*)(X + (size_t)n0 * K))[i4];
    __syncthreads();

    const int cg = tid % CG;
    const int part = tid / CG;
    const int nbase = part * NP;
    const ulonglong2* WA2 = (const ulonglong2*)sm;
    const ulonglong2* WB2 = (const ulonglong2*)(sm + HW);

    float4 avs0, avs1, avd0, avd1;
    if (SC) {
        avs0 = *(const float4*)&att_s[cg * 8];
        avs1 = *(const float4*)&att_s[cg * 8 + 4];
        avd0 = *(const float4*)&att_d[cg * 8];
        avd1 = *(const float4*)&att_d[cg * 8 + 4];
    }

    for (int nb = 0; nb < NP; nb += NSTEP) {
        ull a2[NSTEP][4];
#pragma unroll
        for (int j = 0; j < NSTEP; j++)
#pragma unroll
            for (int q = 0; q < 4; q++) a2[j][q] = 0ull;

#pragma unroll 2
        for (int k0 = 0; k0 < K; k0 += 4) {
            float4 xv[NSTEP];
#pragma unroll
            for (int j = 0; j < NSTEP; j++)
                xv[j] = *(const float4*)&Xs[(nbase + nb + j) * K + k0];
#pragma unroll
            for (int kk = 0; kk < 4; kk++) {
                ulonglong2 wA = WA2[(k0 + kk) * CG + cg];
                ulonglong2 wB = WB2[(k0 + kk) * CG + cg];
#pragma unroll
                for (int j = 0; j < NSTEP; j++) {
                    float xk = (kk == 0) ? xv[j].x : (kk == 1) ? xv[j].y
                             : (kk == 2) ? xv[j].z : xv[j].w;
                    ull xx = pack2(xk, xk);
                    a2[j][0] = ffma2(xx, wA.x, a2[j][0]);
                    a2[j][1] = ffma2(xx, wA.y, a2[j][1]);
                    a2[j][2] = ffma2(xx, wB.x, a2[j][2]);
                    a2[j][3] = ffma2(xx, wB.y, a2[j][3]);
                }
            }
        }
#pragma unroll
        for (int j = 0; j < NSTEP; j++) {
            int n = nbase + nb + j;
            float f0, f1, f2, f3, f4, f5, f6, f7;
            unpack2(a2[j][0], f0, f1); unpack2(a2[j][1], f2, f3);
            unpack2(a2[j][2], f4, f5); unpack2(a2[j][3], f6, f7);
            if (SC) {
                constexpr int C = M / 4;
                constexpr int RG = C / 8;
                float ps = f0 * avs0.x + f1 * avs0.y + f2 * avs0.z + f3 * avs0.w
                         + f4 * avs1.x + f5 * avs1.y + f6 * avs1.z + f7 * avs1.w;
                float pd = f0 * avd0.x + f1 * avd0.y + f2 * avd0.z + f3 * avd0.w
                         + f4 * avd1.x + f5 * avd1.y + f6 * avd1.z + f7 * avd1.w;
#pragma unroll
                for (int o = 1; o < RG; o <<= 1) {
                    ps += __shfl_xor_sync(0xffffffffu, ps, o);
                    pd += __shfl_xor_sync(0xffffffffu, pd, o);
                }
                if ((cg & (RG - 1)) == 0 && n < nn) {
                    int h = (cg * 8) / C;
                    as_[(size_t)(n0 + n) * 4 + h] = ps;
                    ad_[(size_t)(n0 + n) * 4 + h] = pd;
                }
            }
            if (n < nn) {
                if (HALF_OUT) {
                    uint4 o;
                    o.x = h2bits(f0, f1); o.y = h2bits(f2, f3);
                    o.z = h2bits(f4, f5); o.w = h2bits(f6, f7);
                    ((uint4*)Yv)[(size_t)(n0 + n) * (M / 8) + cg] = o;
                } else {
                    float* yp = (float*)Yv + (size_t)(n0 + n) * M + cg * 8;
                    *(ulonglong2*)yp = make_ulonglong2(pack2(f0, f1), pack2(f2, f3));
                    *(ulonglong2*)(yp + 4) = make_ulonglong2(pack2(f4, f5), pack2(f6, f7));
                }
            }
        }
    }
}

// ---- CSR aggregation C=64 (layer 1): 2x-unrolled loop, f32x2 accumulate; node range ----
__launch_bounds__(256)
__global__ void agg_csr64(const int2* __restrict__ eid, const int* __restrict__ ptr,
                          const int* __restrict__ deg, const __half* __restrict__ xlh,
                          const float* __restrict__ as_, const float* __restrict__ ad_,
                          const float* __restrict__ bias, float* __restrict__ out,
                          int n0off, int nEnd) {
    int n = n0off + blockIdx.x * 8 + (threadIdx.x >> 5);
    if (n >= nEnd) return;
    int lane = threadIdx.x & 31;
    int h = lane >> 3;                    // head of this lane's 8 cols
    int p0 = ptr[n], dg = deg[n];
    float adh = ad_[(size_t)n * 4 + h];
    ull acc2[4];
#pragma unroll
    for (int i = 0; i < 4; i++) acc2[i] = 0ull;
    float den = 0.f;
    const uint4* xl4 = (const uint4*)xlh;   // 32 uint4 per row

    int j = 0;
    for (; j + 2 <= dg; j += 2) {
        int2 ea = eid[p0 + j];
        int2 eb = eid[p0 + j + 1];
        float ra = as_[(size_t)ea.y * 4 + h];
        float rb = as_[(size_t)eb.y * 4 + h];
        uint4 va = xl4[(size_t)ea.y * 32 + lane];
        uint4 vb = xl4[(size_t)eb.y * 32 + lane];
        float wa = leaky_exp(ra + adh);
        float wb = leaky_exp(rb + adh);
        den += wa + wb;
        ull wa2 = pack2(wa, wa), wb2 = pack2(wb, wb);
        const __half2* ha = (const __half2*)&va;
        const __half2* hb = (const __half2*)&vb;
#pragma unroll
        for (int i = 0; i < 4; i++) {
            float2 fa = __half22float2(ha[i]);
            float2 fb = __half22float2(hb[i]);
            acc2[i] = ffma2(pack2(fa.x, fa.y), wa2, acc2[i]);
            acc2[i] = ffma2(pack2(fb.x, fb.y), wb2, acc2[i]);
        }
    }
    if (j < dg) {
        int2 e = eid[p0 + j];
        float w = leaky_exp(as_[(size_t)e.y * 4 + h] + adh);
        den += w;
        uint4 v = xl4[(size_t)e.y * 32 + lane];
        ull ww = pack2(w, w);
        const __half2* hp = (const __half2*)&v;
#pragma unroll
        for (int i = 0; i < 4; i++) {
            float2 f = __half22float2(hp[i]);
            acc2[i] = ffma2(pack2(f.x, f.y), ww, acc2[i]);
        }
    }
    float acc[8];
#pragma unroll
    for (int i = 0; i < 4; i++) unpack2(acc2[i], acc[2 * i], acc[2 * i + 1]);
    float dh = 1.f / (den + 1e-16f);
#pragma unroll
    for (int i = 0; i < 8; i++) {
        acc[i] *= dh;
        acc[i] += __shfl_xor_sync(0xffffffffu, acc[i], 8);
        acc[i] += __shfl_xor_sync(0xffffffffu, acc[i], 16);
    }
    if (lane < 8) {
        float* op = out + (size_t)n * 64 + 8 * lane;
        const float* bp = bias + 8 * lane;
        float4 o0, o1;
        o0.x = 0.25f * acc[0] + bp[0]; o0.y = 0.25f * acc[1] + bp[1];
        o0.z = 0.25f * acc[2] + bp[2]; o0.w = 0.25f * acc[3] + bp[3];
        o1.x = 0.25f * acc[4] + bp[4]; o1.y = 0.25f * acc[5] + bp[5];
        o1.z = 0.25f * acc[6] + bp[6]; o1.w = 0.25f * acc[7] + bp[7];
        *(float4*)op = o0;
        *(float4*)(op + 4) = o1;
    }
}

// ---- CSR aggregation C=32 (layer 2): 2x-unrolled, f32x2; exports ex2/den2; node range ----
__launch_bounds__(256)
__global__ void agg_csr32(const int2* __restrict__ eid, const int* __restrict__ ptr,
                          const int* __restrict__ deg, const __half* __restrict__ xlh,
                          const float* __restrict__ as_, const float* __restrict__ ad_,
                          const float* __restrict__ bias, float* __restrict__ out,
                          float* __restrict__ ex2, float* __restrict__ den2,
                          int n0off, int nEnd) {
    int n = n0off + blockIdx.x * 8 + (threadIdx.x >> 5);
    if (n >= nEnd) return;
    int lane = threadIdx.x & 31;
    int h = lane >> 3;                    // head of this lane's 4 cols
    int p0 = ptr[n], dg = deg[n];
    float adh = ad_[(size_t)n * 4 + h];
    ull acc2[2];
    acc2[0] = 0ull; acc2[1] = 0ull;
    float den = 0.f;
    const uint2* xl2 = (const uint2*)xlh;   // 32 uint2 per row

    int j = 0;
    for (; j + 2 <= dg; j += 2) {
        int2 ea = eid[p0 + j];
        int2 eb = eid[p0 + j + 1];
        float ra = as_[(size_t)ea.y * 4 + h];
        float rb = as_[(size_t)eb.y * 4 + h];
        uint2 va = xl2[(size_t)ea.y * 32 + lane];
        uint2 vb = xl2[(size_t)eb.y * 32 + lane];
        float wa = leaky_exp(ra + adh);
        float wb = leaky_exp(rb + adh);
        den += wa + wb;
        if ((lane & 7) == 0) {
            ex2[(size_t)ea.x * 4 + h] = wa;
            ex2[(size_t)eb.x * 4 + h] = wb;
        }
        ull wa2 = pack2(wa, wa), wb2 = pack2(wb, wb);
        const __half2* ha = (const __half2*)&va;
        const __half2* hb = (const __half2*)&vb;
#pragma unroll
        for (int i = 0; i < 2; i++) {
            float2 fa = __half22float2(ha[i]);
            float2 fb = __half22float2(hb[i]);
            acc2[i] = ffma2(pack2(fa.x, fa.y), wa2, acc2[i]);
            acc2[i] = ffma2(pack2(fb.x, fb.y), wb2, acc2[i]);
        }
    }
    if (j < dg) {
        int2 e = eid[p0 + j];
        float w = leaky_exp(as_[(size_t)e.y * 4 + h] + adh);
        den += w;
        if ((lane & 7) == 0) ex2[(size_t)e.x * 4 + h] = w;
        uint2 v = xl2[(size_t)e.y * 32 + lane];
        ull ww = pack2(w, w);
        const __half2* hp = (const __half2*)&v;
#pragma unroll
        for (int i = 0; i < 2; i++) {
            float2 f = __half22float2(hp[i]);
            acc2[i] = ffma2(pack2(f.x, f.y), ww, acc2[i]);
        }
    }
    if ((lane & 7) == 0) den2[(size_t)n * 4 + h] = den;
    float acc[4];
    unpack2(acc2[0], acc[0], acc[1]);
    unpack2(acc2[1], acc[2], acc[3]);
    float dh = 1.f / (den + 1e-16f);
#pragma unroll
    for (int i = 0; i < 4; i++) {
        acc[i] *= dh;
        acc[i] += __shfl_xor_sync(0xffffffffu, acc[i], 8);
        acc[i] += __shfl_xor_sync(0xffffffffu, acc[i], 16);
    }
    if (lane < 8) {
        const float* bp = bias + 4 * lane;
        float4 o;
        o.x = 0.25f * acc[0] + bp[0]; o.y = 0.25f * acc[1] + bp[1];
        o.z = 0.25f * acc[2] + bp[2]; o.w = 0.25f * acc[3] + bp[3];
        *(float4*)(out + (size_t)n * 32 + 4 * lane) = o;
    }
}

// ---------------- edge MLP (decomposed, fp16 P/Q, f32x2 hidden): relu(P[s]+Q[d]+alpha@B+b1) @ W2 ----------------
__launch_bounds__(256)
__global__ void edge_mlp2_kernel(const int* __restrict__ src, const int* __restrict__ dst,
                                 const __half* __restrict__ PQ,
                                 const float* __restrict__ ex2, const float* __restrict__ den2,
                                 const float* __restrict__ mW1, const float* __restrict__ mb1,
                                 const float* __restrict__ mW2, const float* __restrict__ mb2,
                                 float* __restrict__ eo) {
    __shared__ __align__(8) float W1B[4 * 64];   // rows 32..35 of mW1 (alpha part)
    __shared__ __align__(8) float B1[64];
    __shared__ ull W2p[64];         // (W2[j][0], W2[j][1]) pairs
    __shared__ float B2[2];
    int tid = threadIdx.x;
    for (int i = tid; i < 256; i += 256) W1B[i] = mW1[32 * 64 + i];
    if (tid < 64) B1[tid] = mb1[tid];
    if (tid < 128) ((float*)W2p)[tid] = mW2[tid];
    if (tid < 2) B2[tid] = mb2[tid];
    __syncthreads();

    int e = blockIdx.x * 256 + tid;
    if (e >= EE) return;
    int s = src[e], d = dst[e];

    float4 a4 = *(const float4*)(ex2 + (size_t)e * 4);
    float4 dn = *(const float4*)(den2 + (size_t)d * 4);
    ull al0_2, al1_2, al2_2, al3_2;
    {
        float al0 = a4.x / (dn.x + 1e-16f);
        float al1 = a4.y / (dn.y + 1e-16f);
        float al2 = a4.z / (dn.z + 1e-16f);
        float al3 = a4.w / (dn.w + 1e-16f);
        al0_2 = pack2(al0, al0); al1_2 = pack2(al1, al1);
        al2_2 = pack2(al2, al2); al3_2 = pack2(al3, al3);
    }

    const ull* B1p = (const ull*)B1;       // pair j2 = (B1[2j2], B1[2j2+1])
    const ull* W1Bp = (const ull*)W1B;     // row h at W1Bp[h*32 + j2]

    const uint4* PQh = (const uint4*)PQ;  // 16 uint4 per node row (128 halves)
    size_t bs = (size_t)s * 16;           // P: cols 0..63  -> uint4 idx 0..7
    size_t bd = (size_t)d * 16 + 8;       // Q: cols 64..127 -> uint4 idx 0..7

    ull o2 = pack2(B2[0], B2[1]);
#pragma unroll
    for (int qq = 0; qq < 8; qq++) {
        uint4 ph = PQh[bs + qq];
        uint4 qh = PQh[bd + qq];
        const __half2* php = (const __half2*)&ph;
        const __half2* qhp = (const __half2*)&qh;
#pragma unroll
        for (int u2 = 0; u2 < 4; u2++) {
            int j2 = qq * 4 + u2;          // hidden pair 0..31
            float2 pf = __half22float2(php[u2]);
            float2 qf = __half22float2(qhp[u2]);
            ull hv2 = add2(pack2(pf.x + qf.x, pf.y + qf.y), B1p[j2]);
            hv2 = ffma2(al0_2, W1Bp[j2], hv2);
            hv2 = ffma2(al1_2, W1Bp[32 + j2], hv2);
            hv2 = ffma2(al2_2, W1Bp[64 + j2], hv2);
            hv2 = ffma2(al3_2, W1Bp[96 + j2], hv2);
            float h0, h1;
            unpack2(hv2, h0, h1);
            h0 = fmaxf(h0, 0.f); h1 = fmaxf(h1, 0.f);
            o2 = ffma2(pack2(h0, h0), W2p[2 * j2], o2);
            o2 = ffma2(pack2(h1, h1), W2p[2 * j2 + 1], o2);
        }
    }
    float o0, o1;
    unpack2(o2, o0, o1);
    ((float2*)eo)[e] = make_float2(o0, o1);
}

// ---------------- launch ----------------
extern "C" void kernel_launch(void* const* d_in, const int* in_sizes, int n_in,
                              void* d_out, int out_size) {
    const float* x    = (const float*)d_in[0];
    const int*   ei   = (const int*)d_in[1];
    const float* W1   = (const float*)d_in[4];
    const float* a1s  = (const float*)d_in[5];
    const float* a1d  = (const float*)d_in[6];
    const float* b1   = (const float*)d_in[7];
    const float* W3   = (const float*)d_in[8];
    const float* a3s  = (const float*)d_in[9];
    const float* a3d  = (const float*)d_in[10];
    const float* b3   = (const float*)d_in[11];
    const float* mW1  = (const float*)d_in[12];
    const float* mb1  = (const float*)d_in[13];
    const float* mW2  = (const float*)d_in[14];
    const float* mb2  = (const float*)d_in[15];

    const int* src = ei;
    const int* dst = ei + EE;

    float* out_nodes = (float*)d_out;             // N*32
    float* out_edges = (float*)d_out + NN * 32;   // E*2

    __half *p_xl1h, *p_xl2h, *p_pqh;
    float *p_x2, *p_a1s, *p_a1d, *p_a2s, *p_a2d, *p_ex2;
    float *p_den2, *p_wpq;
    int *p_deg, *p_ptr, *p_pos, *p_bsum;
    int2 *p_eid;
    cudaGetSymbolAddress((void**)&p_xl1h, g_xl1h);
    cudaGetSymbolAddress((void**)&p_xl2h, g_xl2h);
    cudaGetSymbolAddress((void**)&p_x2,  g_x2);
    cudaGetSymbolAddress((void**)&p_a1s, g_a1s);
    cudaGetSymbolAddress((void**)&p_a1d, g_a1d);
    cudaGetSymbolAddress((void**)&p_a2s, g_a2s);
    cudaGetSymbolAddress((void**)&p_a2d, g_a2d);
    cudaGetSymbolAddress((void**)&p_ex2, g_ex2);
    cudaGetSymbolAddress((void**)&p_den2, g_den2);
    cudaGetSymbolAddress((void**)&p_pqh, g_pqh);
    cudaGetSymbolAddress((void**)&p_wpq, g_wpq);
    cudaGetSymbolAddress((void**)&p_deg, g_deg);
    cudaGetSymbolAddress((void**)&p_ptr, g_ptr);
    cudaGetSymbolAddress((void**)&p_pos, g_pos);
    cudaGetSymbolAddress((void**)&p_bsum, g_bsum);
    cudaGetSymbolAddress((void**)&p_eid, g_eid);

    static cudaStream_t s2 = nullptr;
    static cudaEvent_t evFork = nullptr, evJoin = nullptr, evG = nullptr, evP = nullptr;
    static cudaEvent_t evA[4], evB[2];
    if (!s2) {
        cudaStreamCreateWithFlags(&s2, cudaStreamNonBlocking);
        cudaEventCreateWithFlags(&evFork, cudaEventDisableTiming);
        cudaEventCreateWithFlags(&evJoin, cudaEventDisableTiming);
        cudaEventCreateWithFlags(&evG, cudaEventDisableTiming);
        cudaEventCreateWithFlags(&evP, cudaEventDisableTiming);
        for (int c = 0; c < 4; c++) cudaEventCreateWithFlags(&evA[c], cudaEventDisableTiming);
        for (int c = 0; c < 2; c++) cudaEventCreateWithFlags(&evB[c], cudaEventDisableTiming);
    }

    const int NB = (NN + 511) / 512;  // 98
    const int SMEM1 = (128 * SA + 128 * SB + 512) * 4;  // 204800 B

    cudaMemsetAsync(p_deg, 0, (size_t)NN * 4);
    cudaEventRecord(evFork, 0);                       // fork point
    cudaStreamWaitEvent(s2, evFork, 0);

    // main stream: CSR build chain
    hist_kernel<<<(EE + 255) / 256, 256>>>(dst, p_deg);
    scanA_kernel<<<NB, 512>>>(p_deg, p_ptr, p_bsum);
    scanB_kernel<<<1, 128>>>(p_bsum, NB);

    // side stream: gemm1 tf32 + repack
    cudaFuncSetAttribute((const void*)gemm1_tf32,
                         cudaFuncAttributeMaxDynamicSharedMemorySize, SMEM1);
    gemm1_tf32<<<(NN + 127) / 128, 256, SMEM1, s2>>>(
        x, W1, p_xl1h, a1s, a1d, p_a1s, p_a1d, NN);
    repack_wpq<<<(32 * 128 + 255) / 256, 256, 0, s2>>>(mW1, p_wpq);
    cudaEventRecord(evJoin, s2);

    scanC_kernel<<<NB, 512>>>(p_ptr, p_bsum, p_pos);
    scatter_kernel<<<(EE + 255) / 256, 256>>>(src, dst, p_pos, p_eid);

    cudaStreamWaitEvent(0, evJoin, 0);                // join

    cudaFuncSetAttribute((const void*)gemm_xw<64, 128, 128, 256, 8, true, true>,
                         cudaFuncAttributeMaxDynamicSharedMemorySize, 65536);
    cudaFuncSetAttribute((const void*)gemm_xw<32, 128, 128, 256, 8, true, false>,
                         cudaFuncAttributeMaxDynamicSharedMemorySize, 32768);

    // ---- pipelined: agg64 (main, 4 chunks) ∥ gemm2 (s2, per-chunk) ----
    const int CH1 = 12500;
    for (int c = 0; c < 4; c++) {
        int off = c * CH1;
        agg_csr64<<<(CH1 + 7) / 8, 256>>>(p_eid, p_ptr, p_deg, p_xl1h,
                                          p_a1s, p_a1d, b1, p_x2, off, off + CH1);
        cudaEventRecord(evA[c], 0);
        cudaStreamWaitEvent(s2, evA[c], 0);
        gemm_xw<64, 128, 128, 256, 8, true, true><<<(CH1 + 127) / 128, 256, 65536, s2>>>(
            p_x2 + (size_t)off * 64, W3, p_xl2h + (size_t)off * 128,
            a3s, a3d, p_a2s + (size_t)off * 4, p_a2d + (size_t)off * 4, CH1);
    }
    cudaEventRecord(evG, s2);
    cudaStreamWaitEvent(0, evG, 0);   // agg32 gathers arbitrary src -> needs ALL of gemm2

    // ---- pipelined: agg32 (main, 2 chunks) ∥ pq-gemm (s2, per-chunk) ----
    const int CH2 = 25000;
    for (int c = 0; c < 2; c++) {
        int off = c * CH2;
        agg_csr32<<<(CH2 + 7) / 8, 256>>>(p_eid, p_ptr, p_deg, p_xl2h,
                                          p_a2s, p_a2d, b3, out_nodes,
                                          p_ex2, p_den2, off, off + CH2);
        cudaEventRecord(evB[c], 0);
        cudaStreamWaitEvent(s2, evB[c], 0);
        gemm_xw<32, 128, 128, 256, 8, true, false><<<(CH2 + 127) / 128, 256, 32768, s2>>>(
            out_nodes + (size_t)off * 32, p_wpq, p_pqh + (size_t)off * 128,
            nullptr, nullptr, nullptr, nullptr, CH2);
    }
    cudaEventRecord(evP, s2);
    cudaStreamWaitEvent(0, evP, 0);   // mlp needs all P/Q

    edge_mlp2_kernel<<<(EE + 255) / 256, 256>>>(src, dst, p_pqh, p_ex2, p_den2,
                                                mW1, mb1, mW2, mb2, out_edges);
}

// round 15
// speedup vs baseline: 1.0923x; 1.0923x over previous
#include <cuda_runtime.h>
#include <cuda_fp16.h>
#include <cuda_bf16.h>

#define NN 50000
#define EE 800000
#define HH 4

typedef unsigned long long ull;

// ---------------- scratch ----------------
__device__ __align__(16) __half g_xl1h[NN * 256];
__device__ __align__(16) __half g_xl2h[NN * 128];
__device__ __align__(16) float g_a1s[NN * 4];
__device__ __align__(16) float g_a1d[NN * 4];
__device__ __align__(16) float g_x2[NN * 64];
__device__ __align__(16) float g_a2s[NN * 4];
__device__ __align__(16) float g_a2d[NN * 4];
__device__ __align__(16) float g_ex2[EE * 4];
__device__ __align__(16) float g_den2[NN * 4];
__device__ __align__(16) __half g_pqh[NN * 128];
__device__ __align__(16) float g_wpq[32 * 128];
__device__ int  g_deg[NN];
__device__ int  g_ptr[NN];
__device__ int  g_pos[NN];
__device__ int  g_bsum[128];
__device__ __align__(8) int2 g_eid[EE];

__device__ __forceinline__ ull ffma2(ull a, ull b, ull c) {
    ull d;
    asm("fma.rn.f32x2 %0, %1, %2, %3;" : "=l"(d) : "l"(a), "l"(b), "l"(c));
    return d;
}
__device__ __forceinline__ ull add2(ull a, ull b) {
    ull d;
    asm("add.rn.f32x2 %0, %1, %2;" : "=l"(d) : "l"(a), "l"(b));
    return d;
}
__device__ __forceinline__ ull pack2(float x, float y) {
    ull d; asm("mov.b64 %0, {%1, %2};" : "=l"(d) : "f"(x), "f"(y)); return d;
}
__device__ __forceinline__ void unpack2(ull v, float& x, float& y) {
    asm("mov.b64 {%0, %1}, %2;" : "=f"(x), "=f"(y) : "l"(v));
}
__device__ __forceinline__ unsigned h2bits(float a, float b) {
    __half2 h = __floats2half2_rn(a, b);
    return *reinterpret_cast<unsigned*>(&h);
}
__device__ __forceinline__ float leaky_exp(float t) {
    t = fmaxf(t, 0.f) + 0.2f * fminf(t, 0.f);
    return __expf(t);
}
__device__ __forceinline__ unsigned tf32b(float f) {
    unsigned r; asm("cvt.rna.tf32.f32 %0, %1;" : "=r"(r) : "f"(f)); return r;
}

// ---------------- CSR build ----------------
__global__ void hist_kernel(const int* __restrict__ dst, int* __restrict__ deg) {
    int e = blockIdx.x * blockDim.x + threadIdx.x;
    if (e < EE) atomicAdd(&deg[dst[e]], 1);
}
__global__ void scanA_kernel(const int* __restrict__ deg, int* __restrict__ out,
                             int* __restrict__ bsum) {
    __shared__ int sm[512];
    int t = threadIdx.x;
    int g = blockIdx.x * 512 + t;
    int v = (g < NN) ? deg[g] : 0;
    sm[t] = v; __syncthreads();
    for (int o = 1; o < 512; o <<= 1) {
        int tt = (t >= o) ? sm[t - o] : 0;
        __syncthreads();
        sm[t] += tt;
        __syncthreads();
    }
    if (g < NN) out[g] = sm[t] - v;            // exclusive
    if (t == 511) bsum[blockIdx.x] = sm[511];
}
__global__ void scanB_kernel(int* __restrict__ bsum, int nb) {
    __shared__ int sm[128];
    int t = threadIdx.x;
    int v = (t < nb) ? bsum[t] : 0;
    sm[t] = v; __syncthreads();
    for (int o = 1; o < 128; o <<= 1) {
        int tt = (t >= o) ? sm[t - o] : 0;
        __syncthreads();
        sm[t] += tt;
        __syncthreads();
    }
    if (t < nb) bsum[t] = sm[t] - v;           // exclusive
}
__global__ void scanC_kernel(int* __restrict__ ptr, const int* __restrict__ bsum,
                             int* __restrict__ pos) {
    int g = blockIdx.x * 512 + threadIdx.x;
    if (g < NN) {
        int v = ptr[g] + bsum[blockIdx.x];
        ptr[g] = v;
        pos[g] = v;
    }
}
__global__ void scatter_kernel(const int* __restrict__ src, const int* __restrict__ dst,
                               int* __restrict__ pos, int2* __restrict__ eid) {
    int e = blockIdx.x * blockDim.x + threadIdx.x;
    if (e < EE) {
        int p = atomicAdd(&pos[dst[e]], 1);
        eid[p] = make_int2(e, src[e]);
    }
}

// -------- repack mW1 rows {0..31}->cols 0..63, rows {36..67}->cols 64..127 --------
__global__ void repack_wpq(const float* __restrict__ mW1, float* __restrict__ wpq) {
    int idx = blockIdx.x * blockDim.x + threadIdx.x;
    if (idx >= 32 * 128) return;
    int k = idx / 128, j = idx % 128;
    wpq[idx] = (j < 64) ? mW1[k * 64 + j] : mW1[(36 + k) * 64 + (j - 64)];
}

// ---------------- gemm1 via tf32 mma.sync (R10 config): Y[N,256] = X[N,128] @ W1[128,256] ----------------
#define SA 132
#define SB 264

#define LOAD_FRAGS(AF, BF, KC)                                              \
    do {                                                                    \
        int _kc = (KC);                                                     \
        _Pragma("unroll")                                                   \
        for (int mt = 0; mt < 4; mt++) {                                    \
            const float* ar = &Asm[(rwarp + mt * 16 + g) * SA + _kc];       \
            AF[mt][0] = __float_as_uint(ar[0]);                             \
            AF[mt][1] = __float_as_uint(ar[8 * SA]);                        \
            AF[mt][2] = __float_as_uint(ar[4]);                             \
            AF[mt][3] = __float_as_uint(ar[8 * SA + 4]);                    \
        }                                                                   \
        const float* br = &Bsm[(size_t)_kc * SB + cwarp + g];               \
        _Pragma("unroll")                                                   \
        for (int n8 = 0; n8 < 8; n8++) {                                    \
            BF[n8][0] = __float_as_uint(br[n8 * 8]);                        \
            BF[n8][1] = __float_as_uint(br[4 * SB + n8 * 8]);               \
        }                                                                   \
    } while (0)

#define MMA_FRAGS(AF, BF)                                                   \
    do {                                                                    \
        _Pragma("unroll")                                                   \
        for (int n8 = 0; n8 < 8; n8++)                                      \
            _Pragma("unroll")                                               \
            for (int mt = 0; mt < 4; mt++) {                                \
                asm volatile(                                               \
                    "mma.sync.aligned.m16n8k8.row.col.f32.tf32.tf32.f32 "  \
                    "{%0,%1,%2,%3}, {%4,%5,%6,%7}, {%8,%9}, {%0,%1,%2,%3};" \
                    : "+f"(acc[mt][n8][0]), "+f"(acc[mt][n8][1]),           \
                      "+f"(acc[mt][n8][2]), "+f"(acc[mt][n8][3])            \
                    : "r"(AF[mt][0]), "r"(AF[mt][1]),                       \
                      "r"(AF[mt][2]), "r"(AF[mt][3]),                       \
                      "r"(BF[n8][0]), "r"(BF[n8][1]));                      \
            }                                                               \
    } while (0)

__global__ __launch_bounds__(256, 1)
void gemm1_tf32(const float* __restrict__ X, const float* __restrict__ W,
                __half* __restrict__ Y,
                const float* __restrict__ att_s, const float* __restrict__ att_d,
                float* __restrict__ as_, float* __restrict__ ad_, int nN) {
    extern __shared__ float sm[];
    float* Asm = sm;                       // 128 x SA
    float* Bsm = sm + 128 * SA;            // 128 x SB
    float* satt = Bsm + 128 * SB;          // [0:256) att_s, [256:512) att_d
    const int tid = threadIdx.x;
    const int n0 = blockIdx.x * 128;
    const int nn = min(128, nN - n0);

    for (int i4 = tid; i4 < 128 * 32; i4 += 256) {
        int r = i4 >> 5, c4 = (i4 & 31) << 2;
        float4 v = (r < nn) ? *(const float4*)&X[(size_t)(n0 + r) * 128 + c4]
                            : make_float4(0.f, 0.f, 0.f, 0.f);
        uint4 u;
        u.x = tf32b(v.x); u.y = tf32b(v.y); u.z = tf32b(v.z); u.w = tf32b(v.w);
        *(uint4*)&Asm[r * SA + c4] = u;
    }
    for (int i4 = tid; i4 < 128 * 64; i4 += 256) {
        int k = i4 >> 6, c4 = (i4 & 63) << 2;
        float4 v = *(const float4*)&W[k * 256 + c4];
        uint4 u;
        u.x = tf32b(v.x); u.y = tf32b(v.y); u.z = tf32b(v.z); u.w = tf32b(v.w);
        *(uint4*)&Bsm[k * SB + c4] = u;
    }
    satt[tid] = att_s[tid];
    satt[256 + tid] = att_d[tid];
    __syncthreads();

    const int w = tid >> 5, lane = tid & 31;
    const int g = lane >> 2, t = lane & 3;
    const int wm = w & 1, wn = w >> 1;           // 2 x 4 warp grid
    const int rwarp = wm * 64;
    const int cwarp = wn * 64;

    float acc[4][8][4];
#pragma unroll
    for (int mt = 0; mt < 4; mt++)
#pragma unroll
        for (int n8 = 0; n8 < 8; n8++)
#pragma unroll
            for (int q = 0; q < 4; q++) acc[mt][n8][q] = 0.f;

    unsigned af0[4][4], bf0[8][2], af1[4][4], bf1[8][2];

    LOAD_FRAGS(af0, bf0, t);                       // k8 = 0
#pragma unroll 1
    for (int k8 = 0; k8 < 16; k8 += 2) {
        LOAD_FRAGS(af1, bf1, (k8 + 1) * 8 + t);
        MMA_FRAGS(af0, bf0);
        if (k8 + 2 < 16) LOAD_FRAGS(af0, bf0, (k8 + 2) * 8 + t);
        MMA_FRAGS(af1, bf1);
    }

#pragma unroll
    for (int mt = 0; mt < 4; mt++) {
        float ps0 = 0.f, pd0 = 0.f, ps1 = 0.f, pd1 = 0.f;
#pragma unroll
        for (int n8 = 0; n8 < 8; n8++) {
            int col = cwarp + n8 * 8 + 2 * t;
            float s0 = satt[col], s1 = satt[col + 1];
            float d0 = satt[256 + col], d1 = satt[256 + col + 1];
            ps0 += acc[mt][n8][0] * s0 + acc[mt][n8][1] * s1;
            pd0 += acc[mt][n8][0] * d0 + acc[mt][n8][1] * d1;
            ps1 += acc[mt][n8][2] * s0 + acc[mt][n8][3] * s1;
            pd1 += acc[mt][n8][2] * d0 + acc[mt][n8][3] * d1;
        }
#pragma unroll
        for (int o = 1; o <= 2; o <<= 1) {
            ps0 += __shfl_xor_sync(0xffffffffu, ps0, o);
            pd0 += __shfl_xor_sync(0xffffffffu, pd0, o);
            ps1 += __shfl_xor_sync(0xffffffffu, ps1, o);
            pd1 += __shfl_xor_sync(0xffffffffu, pd1, o);
        }
        int m0 = n0 + rwarp + mt * 16 + g;
        int m1 = m0 + 8;
        if (t == 0) {
            if (m0 < nN) { as_[(size_t)m0 * 4 + wn] = ps0; ad_[(size_t)m0 * 4 + wn] = pd0; }
            if (m1 < nN) { as_[(size_t)m1 * 4 + wn] = ps1; ad_[(size_t)m1 * 4 + wn] = pd1; }
        }
        bool w0 = (m0 < nN), w1 = (m1 < nN);
#pragma unroll
        for (int n8 = 0; n8 < 8; n8++) {
            int col = cwarp + n8 * 8 + 2 * t;
            if (w0) *(unsigned*)&Y[(size_t)m0 * 256 + col] = h2bits(acc[mt][n8][0], acc[mt][n8][1]);
            if (w1) *(unsigned*)&Y[(size_t)m1 * 256 + col] = h2bits(acc[mt][n8][2], acc[mt][n8][3]);
        }
    }
}

// ---------------- GEMM (FFMA2 path, used for layer2 + PQ): Y[N,M] = X[N,K] @ W[K,M] ----------------
template <int K, int M, int TN, int TH, int NSTEP, bool HALF_OUT, bool SC>
__launch_bounds__(TH, 1)
__global__ void gemm_xw(const float* __restrict__ X, const float* __restrict__ W,
                        void* __restrict__ Yv,
                        const float* __restrict__ att_s, const float* __restrict__ att_d,
                        float* __restrict__ as_, float* __restrict__ ad_, int nN) {
    extern __shared__ float sm[];
    constexpr int CG = M / 8;
    constexpr int PARTS = TH / CG;
    constexpr int NP = TN / PARTS;
    constexpr int HW = K * M / 2;
    static_assert(NP % NSTEP == 0, "NP % NSTEP");
    float* Xs = sm + K * M;
    const int tid = threadIdx.x;

    for (int i4 = tid; i4 < K * M / 4; i4 += TH) {
        int i = i4 * 4;
        int k = i / M, c = i % M;
        float4 v = *(const float4*)&W[i];
        int grp = (c >> 2) & 1;
        int d = (k * (M / 8) + (c >> 3)) * 4;
        *(float4*)&sm[(grp ? HW : 0) + d] = v;
    }
    const int n0 = blockIdx.x * TN;
    const int nn = min(TN, nN - n0);
    for (int i4 = tid; i4 < nn * K / 4; i4 += TH)
        ((float4*)Xs)[i4] = ((const float4*)(X + (size_t)n0 * K))[i4];
    __syncthreads();

    const int cg = tid % CG;
    const int part = tid / CG;
    const int nbase = part * NP;
    const ulonglong2* WA2 = (const ulonglong2*)sm;
    const ulonglong2* WB2 = (const ulonglong2*)(sm + HW);

    float4 avs0, avs1, avd0, avd1;
    if (SC) {
        avs0 = *(const float4*)&att_s[cg * 8];
        avs1 = *(const float4*)&att_s[cg * 8 + 4];
        avd0 = *(const float4*)&att_d[cg * 8];
        avd1 = *(const float4*)&att_d[cg * 8 + 4];
    }

    for (int nb = 0; nb < NP; nb += NSTEP) {
        ull a2[NSTEP][4];
#pragma unroll
        for (int j = 0; j < NSTEP; j++)
#pragma unroll
            for (int q = 0; q < 4; q++) a2[j][q] = 0ull;

#pragma unroll 2
        for (int k0 = 0; k0 < K; k0 += 4) {
            float4 xv[NSTEP];
#pragma unroll
            for (int j = 0; j < NSTEP; j++)
                xv[j] = *(const float4*)&Xs[(nbase + nb + j) * K + k0];
#pragma unroll
            for (int kk = 0; kk < 4; kk++) {
                ulonglong2 wA = WA2[(k0 + kk) * CG + cg];
                ulonglong2 wB = WB2[(k0 + kk) * CG + cg];
#pragma unroll
                for (int j = 0; j < NSTEP; j++) {
                    float xk = (kk == 0) ? xv[j].x : (kk == 1) ? xv[j].y
                             : (kk == 2) ? xv[j].z : xv[j].w;
                    ull xx = pack2(xk, xk);
                    a2[j][0] = ffma2(xx, wA.x, a2[j][0]);
                    a2[j][1] = ffma2(xx, wA.y, a2[j][1]);
                    a2[j][2] = ffma2(xx, wB.x, a2[j][2]);
                    a2[j][3] = ffma2(xx, wB.y, a2[j][3]);
                }
            }
        }
#pragma unroll
        for (int j = 0; j < NSTEP; j++) {
            int n = nbase + nb + j;
            float f0, f1, f2, f3, f4, f5, f6, f7;
            unpack2(a2[j][0], f0, f1); unpack2(a2[j][1], f2, f3);
            unpack2(a2[j][2], f4, f5); unpack2(a2[j][3], f6, f7);
            if (SC) {
                constexpr int C = M / 4;
                constexpr int RG = C / 8;
                float ps = f0 * avs0.x + f1 * avs0.y + f2 * avs0.z + f3 * avs0.w
                         + f4 * avs1.x + f5 * avs1.y + f6 * avs1.z + f7 * avs1.w;
                float pd = f0 * avd0.x + f1 * avd0.y + f2 * avd0.z + f3 * avd0.w
                         + f4 * avd1.x + f5 * avd1.y + f6 * avd1.z + f7 * avd1.w;
#pragma unroll
                for (int o = 1; o < RG; o <<= 1) {
                    ps += __shfl_xor_sync(0xffffffffu, ps, o);
                    pd += __shfl_xor_sync(0xffffffffu, pd, o);
                }
                if ((cg & (RG - 1)) == 0 && n < nn) {
                    int h = (cg * 8) / C;
                    as_[(size_t)(n0 + n) * 4 + h] = ps;
                    ad_[(size_t)(n0 + n) * 4 + h] = pd;
                }
            }
            if (n < nn) {
                if (HALF_OUT) {
                    uint4 o;
                    o.x = h2bits(f0, f1); o.y = h2bits(f2, f3);
                    o.z = h2bits(f4, f5); o.w = h2bits(f6, f7);
                    ((uint4*)Yv)[(size_t)(n0 + n) * (M / 8) + cg] = o;
                } else {
                    float* yp = (float*)Yv + (size_t)(n0 + n) * M + cg * 8;
                    *(ulonglong2*)yp = make_ulonglong2(pack2(f0, f1), pack2(f2, f3));
                    *(ulonglong2*)(yp + 4) = make_ulonglong2(pack2(f4, f5), pack2(f6, f7));
                }
            }
        }
    }
}

// ---- CSR aggregation C=64 (layer 1): 2x-unrolled loop, f32x2 accumulate ----
__launch_bounds__(256)
__global__ void agg_csr64(const int2* __restrict__ eid, const int* __restrict__ ptr,
                          const int* __restrict__ deg, const __half* __restrict__ xlh,
                          const float* __restrict__ as_, const float* __restrict__ ad_,
                          const float* __restrict__ bias, float* __restrict__ out) {
    int n = blockIdx.x * 8 + (threadIdx.x >> 5);
    if (n >= NN) return;
    int lane = threadIdx.x & 31;
    int h = lane >> 3;                    // head of this lane's 8 cols
    int p0 = ptr[n], dg = deg[n];
    float adh = ad_[(size_t)n * 4 + h];
    ull acc2[4];
#pragma unroll
    for (int i = 0; i < 4; i++) acc2[i] = 0ull;
    float den = 0.f;
    const uint4* xl4 = (const uint4*)xlh;   // 32 uint4 per row

    int j = 0;
    for (; j + 2 <= dg; j += 2) {
        int2 ea = eid[p0 + j];
        int2 eb = eid[p0 + j + 1];
        float ra = as_[(size_t)ea.y * 4 + h];
        float rb = as_[(size_t)eb.y * 4 + h];
        uint4 va = xl4[(size_t)ea.y * 32 + lane];
        uint4 vb = xl4[(size_t)eb.y * 32 + lane];
        float wa = leaky_exp(ra + adh);
        float wb = leaky_exp(rb + adh);
        den += wa + wb;
        ull wa2 = pack2(wa, wa), wb2 = pack2(wb, wb);
        const __half2* ha = (const __half2*)&va;
        const __half2* hb = (const __half2*)&vb;
#pragma unroll
        for (int i = 0; i < 4; i++) {
            float2 fa = __half22float2(ha[i]);
            float2 fb = __half22float2(hb[i]);
            acc2[i] = ffma2(pack2(fa.x, fa.y), wa2, acc2[i]);
            acc2[i] = ffma2(pack2(fb.x, fb.y), wb2, acc2[i]);
        }
    }
    if (j < dg) {
        int2 e = eid[p0 + j];
        float w = leaky_exp(as_[(size_t)e.y * 4 + h] + adh);
        den += w;
        uint4 v = xl4[(size_t)e.y * 32 + lane];
        ull ww = pack2(w, w);
        const __half2* hp = (const __half2*)&v;
#pragma unroll
        for (int i = 0; i < 4; i++) {
            float2 f = __half22float2(hp[i]);
            acc2[i] = ffma2(pack2(f.x, f.y), ww, acc2[i]);
        }
    }
    float acc[8];
#pragma unroll
    for (int i = 0; i < 4; i++) unpack2(acc2[i], acc[2 * i], acc[2 * i + 1]);
    float dh = 1.f / (den + 1e-16f);
#pragma unroll
    for (int i = 0; i < 8; i++) {
        acc[i] *= dh;
        acc[i] += __shfl_xor_sync(0xffffffffu, acc[i], 8);
        acc[i] += __shfl_xor_sync(0xffffffffu, acc[i], 16);
    }
    if (lane < 8) {
        float* op = out + (size_t)n * 64 + 8 * lane;
        const float* bp = bias + 8 * lane;
        float4 o0, o1;
        o0.x = 0.25f * acc[0] + bp[0]; o0.y = 0.25f * acc[1] + bp[1];
        o0.z = 0.25f * acc[2] + bp[2]; o0.w = 0.25f * acc[3] + bp[3];
        o1.x = 0.25f * acc[4] + bp[4]; o1.y = 0.25f * acc[5] + bp[5];
        o1.z = 0.25f * acc[6] + bp[6]; o1.w = 0.25f * acc[7] + bp[7];
        *(float4*)op = o0;
        *(float4*)(op + 4) = o1;
    }
}

// ---- CSR aggregation C=32 (layer 2): 2x-unrolled, f32x2; exports ex2/den2 ----
__launch_bounds__(256)
__global__ void agg_csr32(const int2* __restrict__ eid, const int* __restrict__ ptr,
                          const int* __restrict__ deg, const __half* __restrict__ xlh,
                          const float* __restrict__ as_, const float* __restrict__ ad_,
                          const float* __restrict__ bias, float* __restrict__ out,
                          float* __restrict__ ex2, float* __restrict__ den2) {
    int n = blockIdx.x * 8 + (threadIdx.x >> 5);
    if (n >= NN) return;
    int lane = threadIdx.x & 31;
    int h = lane >> 3;                    // head of this lane's 4 cols
    int p0 = ptr[n], dg = deg[n];
    float adh = ad_[(size_t)n * 4 + h];
    ull acc2[2];
    acc2[0] = 0ull; acc2[1] = 0ull;
    float den = 0.f;
    const uint2* xl2 = (const uint2*)xlh;   // 32 uint2 per row

    int j = 0;
    for (; j + 2 <= dg; j += 2) {
        int2 ea = eid[p0 + j];
        int2 eb = eid[p0 + j + 1];
        float ra = as_[(size_t)ea.y * 4 + h];
        float rb = as_[(size_t)eb.y * 4 + h];
        uint2 va = xl2[(size_t)ea.y * 32 + lane];
        uint2 vb = xl2[(size_t)eb.y * 32 + lane];
        float wa = leaky_exp(ra + adh);
        float wb = leaky_exp(rb + adh);
        den += wa + wb;
        if ((lane & 7) == 0) {
            ex2[(size_t)ea.x * 4 + h] = wa;
            ex2[(size_t)eb.x * 4 + h] = wb;
        }
        ull wa2 = pack2(wa, wa), wb2 = pack2(wb, wb);
        const __half2* ha = (const __half2*)&va;
        const __half2* hb = (const __half2*)&vb;
#pragma unroll
        for (int i = 0; i < 2; i++) {
            float2 fa = __half22float2(ha[i]);
            float2 fb = __half22float2(hb[i]);
            acc2[i] = ffma2(pack2(fa.x, fa.y), wa2, acc2[i]);
            acc2[i] = ffma2(pack2(fb.x, fb.y), wb2, acc2[i]);
        }
    }
    if (j < dg) {
        int2 e = eid[p0 + j];
        float w = leaky_exp(as_[(size_t)e.y * 4 + h] + adh);
        den += w;
        if ((lane & 7) == 0) ex2[(size_t)e.x * 4 + h] = w;
        uint2 v = xl2[(size_t)e.y * 32 + lane];
        ull ww = pack2(w, w);
        const __half2* hp = (const __half2*)&v;
#pragma unroll
        for (int i = 0; i < 2; i++) {
            float2 f = __half22float2(hp[i]);
            acc2[i] = ffma2(pack2(f.x, f.y), ww, acc2[i]);
        }
    }
    if ((lane & 7) == 0) den2[(size_t)n * 4 + h] = den;
    float acc[4];
    unpack2(acc2[0], acc[0], acc[1]);
    unpack2(acc2[1], acc[2], acc[3]);
    float dh = 1.f / (den + 1e-16f);
#pragma unroll
    for (int i = 0; i < 4; i++) {
        acc[i] *= dh;
        acc[i] += __shfl_xor_sync(0xffffffffu, acc[i], 8);
        acc[i] += __shfl_xor_sync(0xffffffffu, acc[i], 16);
    }
    if (lane < 8) {
        const float* bp = bias + 4 * lane;
        float4 o;
        o.x = 0.25f * acc[0] + bp[0]; o.y = 0.25f * acc[1] + bp[1];
        o.z = 0.25f * acc[2] + bp[2]; o.w = 0.25f * acc[3] + bp[3];
        *(float4*)(out + (size_t)n * 32 + 4 * lane) = o;
    }
}

// ---------------- edge MLP (decomposed, fp16 P/Q, f32x2 hidden): relu(P[s]+Q[d]+alpha@B+b1) @ W2 ----------------
__launch_bounds__(256)
__global__ void edge_mlp2_kernel(const int* __restrict__ src, const int* __restrict__ dst,
                                 const __half* __restrict__ PQ,
                                 const float* __restrict__ ex2, const float* __restrict__ den2,
                                 const float* __restrict__ mW1, const float* __restrict__ mb1,
                                 const float* __restrict__ mW2, const float* __restrict__ mb2,
                                 float* __restrict__ eo) {
    __shared__ __align__(8) float W1B[4 * 64];   // rows 32..35 of mW1 (alpha part)
    __shared__ __align__(8) float B1[64];
    __shared__ ull W2p[64];         // (W2[j][0], W2[j][1]) pairs
    __shared__ float B2[2];
    int tid = threadIdx.x;
    for (int i = tid; i < 256; i += 256) W1B[i] = mW1[32 * 64 + i];
    if (tid < 64) B1[tid] = mb1[tid];
    if (tid < 128) ((float*)W2p)[tid] = mW2[tid];
    if (tid < 2) B2[tid] = mb2[tid];
    __syncthreads();

    int e = blockIdx.x * 256 + tid;
    if (e >= EE) return;
    int s = src[e], d = dst[e];

    float4 a4 = *(const float4*)(ex2 + (size_t)e * 4);
    float4 dn = *(const float4*)(den2 + (size_t)d * 4);
    ull al0_2, al1_2, al2_2, al3_2;
    {
        float al0 = a4.x / (dn.x + 1e-16f);
        float al1 = a4.y / (dn.y + 1e-16f);
        float al2 = a4.z / (dn.z + 1e-16f);
        float al3 = a4.w / (dn.w + 1e-16f);
        al0_2 = pack2(al0, al0); al1_2 = pack2(al1, al1);
        al2_2 = pack2(al2, al2); al3_2 = pack2(al3, al3);
    }

    const ull* B1p = (const ull*)B1;       // pair j2 = (B1[2j2], B1[2j2+1])
    const ull* W1Bp = (const ull*)W1B;     // row h at W1Bp[h*32 + j2]

    const uint4* PQh = (const uint4*)PQ;  // 16 uint4 per node row (128 halves)
    size_t bs = (size_t)s * 16;           // P: cols 0..63  -> uint4 idx 0..7
    size_t bd = (size_t)d * 16 + 8;       // Q: cols 64..127 -> uint4 idx 0..7

    ull o2 = pack2(B2[0], B2[1]);
#pragma unroll
    for (int qq = 0; qq < 8; qq++) {
        uint4 ph = PQh[bs + qq];
        uint4 qh = PQh[bd + qq];
        const __half2* php = (const __half2*)&ph;
        const __half2* qhp = (const __half2*)&qh;
#pragma unroll
        for (int u2 = 0; u2 < 4; u2++) {
            int j2 = qq * 4 + u2;          // hidden pair 0..31
            float2 pf = __half22float2(php[u2]);
            float2 qf = __half22float2(qhp[u2]);
            ull hv2 = add2(pack2(pf.x + qf.x, pf.y + qf.y), B1p[j2]);
            hv2 = ffma2(al0_2, W1Bp[j2], hv2);
            hv2 = ffma2(al1_2, W1Bp[32 + j2], hv2);
            hv2 = ffma2(al2_2, W1Bp[64 + j2], hv2);
            hv2 = ffma2(al3_2, W1Bp[96 + j2], hv2);
            float h0, h1;
            unpack2(hv2, h0, h1);
            h0 = fmaxf(h0, 0.f); h1 = fmaxf(h1, 0.f);
            o2 = ffma2(pack2(h0, h0), W2p[2 * j2], o2);
            o2 = ffma2(pack2(h1, h1), W2p[2 * j2 + 1], o2);
        }
    }
    float o0, o1;
    unpack2(o2, o0, o1);
    ((float2*)eo)[e] = make_float2(o0, o1);
}

// ---------------- launch ----------------
extern "C" void kernel_launch(void* const* d_in, const int* in_sizes, int n_in,
                              void* d_out, int out_size) {
    const float* x    = (const float*)d_in[0];
    const int*   ei   = (const int*)d_in[1];
    const float* W1   = (const float*)d_in[4];
    const float* a1s  = (const float*)d_in[5];
    const float* a1d  = (const float*)d_in[6];
    const float* b1   = (const float*)d_in[7];
    const float* W3   = (const float*)d_in[8];
    const float* a3s  = (const float*)d_in[9];
    const float* a3d  = (const float*)d_in[10];
    const float* b3   = (const float*)d_in[11];
    const float* mW1  = (const float*)d_in[12];
    const float* mb1  = (const float*)d_in[13];
    const float* mW2  = (const float*)d_in[14];
    const float* mb2  = (const float*)d_in[15];

    const int* src = ei;
    const int* dst = ei + EE;

    float* out_nodes = (float*)d_out;             // N*32
    float* out_edges = (float*)d_out + NN * 32;   // E*2

    __half *p_xl1h, *p_xl2h, *p_pqh;
    float *p_x2, *p_a1s, *p_a1d, *p_a2s, *p_a2d, *p_ex2;
    float *p_den2, *p_wpq;
    int *p_deg, *p_ptr, *p_pos, *p_bsum;
    int2 *p_eid;
    cudaGetSymbolAddress((void**)&p_xl1h, g_xl1h);
    cudaGetSymbolAddress((void**)&p_xl2h, g_xl2h);
    cudaGetSymbolAddress((void**)&p_x2,  g_x2);
    cudaGetSymbolAddress((void**)&p_a1s, g_a1s);
    cudaGetSymbolAddress((void**)&p_a1d, g_a1d);
    cudaGetSymbolAddress((void**)&p_a2s, g_a2s);
    cudaGetSymbolAddress((void**)&p_a2d, g_a2d);
    cudaGetSymbolAddress((void**)&p_ex2, g_ex2);
    cudaGetSymbolAddress((void**)&p_den2, g_den2);
    cudaGetSymbolAddress((void**)&p_pqh, g_pqh);
    cudaGetSymbolAddress((void**)&p_wpq, g_wpq);
    cudaGetSymbolAddress((void**)&p_deg, g_deg);
    cudaGetSymbolAddress((void**)&p_ptr, g_ptr);
    cudaGetSymbolAddress((void**)&p_pos, g_pos);
    cudaGetSymbolAddress((void**)&p_bsum, g_bsum);
    cudaGetSymbolAddress((void**)&p_eid, g_eid);

    static cudaStream_t s2 = nullptr;
    static cudaEvent_t evFork = nullptr, evJoin = nullptr;
    if (!s2) {
        cudaStreamCreateWithFlags(&s2, cudaStreamNonBlocking);
        cudaEventCreateWithFlags(&evFork, cudaEventDisableTiming);
        cudaEventCreateWithFlags(&evJoin, cudaEventDisableTiming);
    }

    const int NB = (NN + 511) / 512;  // 98
    const int SMEM1 = (128 * SA + 128 * SB + 512) * 4;  // 204800 B

    cudaMemsetAsync(p_deg, 0, (size_t)NN * 4);
    cudaEventRecord(evFork, 0);                       // fork point
    cudaStreamWaitEvent(s2, evFork, 0);

    // main stream: CSR build chain
    hist_kernel<<<(EE + 255) / 256, 256>>>(dst, p_deg);
    scanA_kernel<<<NB, 512>>>(p_deg, p_ptr, p_bsum);
    scanB_kernel<<<1, 128>>>(p_bsum, NB);

    // side stream: gemm1 tf32 + repack
    cudaFuncSetAttribute((const void*)gemm1_tf32,
                         cudaFuncAttributeMaxDynamicSharedMemorySize, SMEM1);
    gemm1_tf32<<<(NN + 127) / 128, 256, SMEM1, s2>>>(
        x, W1, p_xl1h, a1s, a1d, p_a1s, p_a1d, NN);
    repack_wpq<<<(32 * 128 + 255) / 256, 256, 0, s2>>>(mW1, p_wpq);
    cudaEventRecord(evJoin, s2);

    scanC_kernel<<<NB, 512>>>(p_ptr, p_bsum, p_pos);
    scatter_kernel<<<(EE + 255) / 256, 256>>>(src, dst, p_pos, p_eid);

    cudaStreamWaitEvent(0, evJoin, 0);                // join

    // Layer 1 aggregation (fused exp/den/finalize)
    agg_csr64<<<(NN + 7) / 8, 256>>>(p_eid, p_ptr, p_deg, p_xl1h,
                                     p_a1s, p_a1d, b1, p_x2);

    // Layer 2
    cudaFuncSetAttribute((const void*)gemm_xw<64, 128, 128, 256, 8, true, true>,
                         cudaFuncAttributeMaxDynamicSharedMemorySize, 65536);
    gemm_xw<64, 128, 128, 256, 8, true, true><<<(NN + 127) / 128, 256, 65536>>>(
        p_x2, W3, p_xl2h, a3s, a3d, p_a2s, p_a2d, NN);
    agg_csr32<<<(NN + 7) / 8, 256>>>(p_eid, p_ptr, p_deg, p_xl2h,
                                     p_a2s, p_a2d, b3, out_nodes,
                                     p_ex2, p_den2);

    // Edge MLP: per-node P/Q precompute (fp16 out), then light per-edge kernel
    cudaFuncSetAttribute((const void*)gemm_xw<32, 128, 128, 256, 8, true, false>,
                         cudaFuncAttributeMaxDynamicSharedMemorySize, 32768);
    gemm_xw<32, 128, 128, 256, 8, true, false><<<(NN + 127) / 128, 256, 32768>>>(
        out_nodes, p_wpq, p_pqh, nullptr, nullptr, nullptr, nullptr, NN);
    edge_mlp2_kernel<<<(EE + 255) / 256, 256>>>(src, dst, p_pqh, p_ex2, p_den2,
                                                mW1, mb1, mW2, mb2, out_edges);
}

// round 16
// speedup vs baseline: 1.1106x; 1.0168x over previous
#include <cuda_runtime.h>
#include <cuda_fp16.h>
#include <cuda_bf16.h>

#define NN 50000
#define EE 800000
#define HH 4

typedef unsigned long long ull;

// ---------------- scratch ----------------
__device__ __align__(16) __half g_xl1h[NN * 256];
__device__ __align__(16) __half g_xl2h[NN * 128];
__device__ __align__(16) float g_a1s[NN * 4];
__device__ __align__(16) float g_a1d[NN * 4];
__device__ __align__(16) float g_x2[NN * 64];
__device__ __align__(16) float g_a2s[NN * 4];
__device__ __align__(16) float g_a2d[NN * 4];
__device__ __align__(16) float g_ex2[EE * 4];
__device__ __align__(16) float g_den2[NN * 4];
__device__ __align__(16) __half g_pqh[NN * 128];
__device__ __align__(16) float g_wpq[32 * 128];
__device__ int  g_deg[NN];
__device__ int  g_ptr[NN];
__device__ int  g_pos[NN];
__device__ int  g_bsum[128];
__device__ __align__(8) int2 g_eid[EE];

__device__ __forceinline__ ull ffma2(ull a, ull b, ull c) {
    ull d;
    asm("fma.rn.f32x2 %0, %1, %2, %3;" : "=l"(d) : "l"(a), "l"(b), "l"(c));
    return d;
}
__device__ __forceinline__ ull add2(ull a, ull b) {
    ull d;
    asm("add.rn.f32x2 %0, %1, %2;" : "=l"(d) : "l"(a), "l"(b));
    return d;
}
__device__ __forceinline__ ull pack2(float x, float y) {
    ull d; asm("mov.b64 %0, {%1, %2};" : "=l"(d) : "f"(x), "f"(y)); return d;
}
__device__ __forceinline__ void unpack2(ull v, float& x, float& y) {
    asm("mov.b64 {%0, %1}, %2;" : "=f"(x), "=f"(y) : "l"(v));
}
__device__ __forceinline__ unsigned h2bits(float a, float b) {
    __half2 h = __floats2half2_rn(a, b);
    return *reinterpret_cast<unsigned*>(&h);
}
__device__ __forceinline__ float leaky_exp(float t) {
    t = fmaxf(t, 0.f) + 0.2f * fminf(t, 0.f);
    return __expf(t);
}

// ---------------- CSR build ----------------
__global__ void hist_kernel(const int* __restrict__ dst, int* __restrict__ deg) {
    int e = blockIdx.x * blockDim.x + threadIdx.x;
    if (e < EE) atomicAdd(&deg[dst[e]], 1);
}
__global__ void scanA_kernel(const int* __restrict__ deg, int* __restrict__ out,
                             int* __restrict__ bsum) {
    __shared__ int sm[512];
    int t = threadIdx.x;
    int g = blockIdx.x * 512 + t;
    int v = (g < NN) ? deg[g] : 0;
    sm[t] = v; __syncthreads();
    for (int o = 1; o < 512; o <<= 1) {
        int tt = (t >= o) ? sm[t - o] : 0;
        __syncthreads();
        sm[t] += tt;
        __syncthreads();
    }
    if (g < NN) out[g] = sm[t] - v;            // exclusive
    if (t == 511) bsum[blockIdx.x] = sm[511];
}
__global__ void scanB_kernel(int* __restrict__ bsum, int nb) {
    __shared__ int sm[128];
    int t = threadIdx.x;
    int v = (t < nb) ? bsum[t] : 0;
    sm[t] = v; __syncthreads();
    for (int o = 1; o < 128; o <<= 1) {
        int tt = (t >= o) ? sm[t - o] : 0;
        __syncthreads();
        sm[t] += tt;
        __syncthreads();
    }
    if (t < nb) bsum[t] = sm[t] - v;           // exclusive
}
__global__ void scanC_kernel(int* __restrict__ ptr, const int* __restrict__ bsum,
                             int* __restrict__ pos) {
    int g = blockIdx.x * 512 + threadIdx.x;
    if (g < NN) {
        int v = ptr[g] + bsum[blockIdx.x];
        ptr[g] = v;
        pos[g] = v;
    }
}
__global__ void scatter_kernel(const int* __restrict__ src, const int* __restrict__ dst,
                               int* __restrict__ pos, int2* __restrict__ eid) {
    int e = blockIdx.x * blockDim.x + threadIdx.x;
    if (e < EE) {
        int p = atomicAdd(&pos[dst[e]], 1);
        eid[p] = make_int2(e, src[e]);
    }
}

// -------- repack mW1 rows {0..31}->cols 0..63, rows {36..67}->cols 64..127 --------
__global__ void repack_wpq(const float* __restrict__ mW1, float* __restrict__ wpq) {
    int idx = blockIdx.x * blockDim.x + threadIdx.x;
    if (idx >= 32 * 128) return;
    int k = idx / 128, j = idx % 128;
    wpq[idx] = (j < 64) ? mW1[k * 64 + j] : mW1[(36 + k) * 64 + (j - 64)];
}

// ---------------- gemm1 via fp16 mma.sync m16n8k16: Y[N,256] = X[N,128] @ W1[128,256] ----------------
// 8 warps = 2(m) x 4(n), warp tile 64x64. 8 k16-steps, double-buffered frags (static idx).
// A: row-major halves, pad PA=136 (word-addr 4g+t conflict-free).
// B: (k,k+1)-interleaved half2 [k2][col], pad PB=264 (word-addr 8t+g conflict-free).
#define PA 136
#define PB 264

#define LOAD_FRAGS16(AF, BF, KK)                                            \
    do {                                                                    \
        int _kh = (KK) * 16 + 2 * t;                                        \
        _Pragma("unroll")                                                   \
        for (int mt = 0; mt < 4; mt++) {                                    \
            const __half* ar = &Ah[(rwarp + mt * 16 + g) * PA + _kh];       \
            AF[mt][0] = *(const unsigned*)(ar);                             \
            AF[mt][1] = *(const unsigned*)(ar + 8 * PA);                    \
            AF[mt][2] = *(const unsigned*)(ar + 8);                         \
            AF[mt][3] = *(const unsigned*)(ar + 8 * PA + 8);                \
        }                                                                   \
        const unsigned* br = &B2u[((KK) * 8 + t) * PB + cwarp + g];         \
        _Pragma("unroll")                                                   \
        for (int n8 = 0; n8 < 8; n8++) {                                    \
            BF[n8][0] = br[n8 * 8];                                         \
            BF[n8][1] = br[4 * PB + n8 * 8];                                \
        }                                                                   \
    } while (0)

#define MMA_FRAGS16(AF, BF)                                                 \
    do {                                                                    \
        _Pragma("unroll")                                                   \
        for (int n8 = 0; n8 < 8; n8++)                                      \
            _Pragma("unroll")                                               \
            for (int mt = 0; mt < 4; mt++) {                                \
                asm volatile(                                               \
                    "mma.sync.aligned.m16n8k16.row.col.f32.f16.f16.f32 "   \
                    "{%0,%1,%2,%3}, {%4,%5,%6,%7}, {%8,%9}, {%0,%1,%2,%3};" \
                    : "+f"(acc[mt][n8][0]), "+f"(acc[mt][n8][1]),           \
                      "+f"(acc[mt][n8][2]), "+f"(acc[mt][n8][3])            \
                    : "r"(AF[mt][0]), "r"(AF[mt][1]),                       \
                      "r"(AF[mt][2]), "r"(AF[mt][3]),                       \
                      "r"(BF[n8][0]), "r"(BF[n8][1]));                      \
            }                                                               \
    } while (0)

__global__ __launch_bounds__(256, 1)
void gemm1_f16(const float* __restrict__ X, const float* __restrict__ W,
               __half* __restrict__ Y,
               const float* __restrict__ att_s, const float* __restrict__ att_d,
               float* __restrict__ as_, float* __restrict__ ad_, int nN) {
    extern __shared__ float sm[];
    __half* Ah = (__half*)sm;               // 128 x PA halves (34816 B = 8704 floats)
    unsigned* B2u = (unsigned*)(sm + 8704); // 64 x PB half2 (67584 B = 16896 floats)
    float* satt = sm + 8704 + 16896;        // [0:256) att_s, [256:512) att_d
    const int tid = threadIdx.x;
    const int n0 = blockIdx.x * 128;
    const int nn = min(128, nN - n0);

    // fill A (X tile), fp16
    for (int i4 = tid; i4 < 128 * 32; i4 += 256) {
        int r = i4 >> 5, c4 = (i4 & 31) << 2;
        float4 v = (r < nn) ? *(const float4*)&X[(size_t)(n0 + r) * 128 + c4]
                            : make_float4(0.f, 0.f, 0.f, 0.f);
        uint2 u;
        u.x = h2bits(v.x, v.y); u.y = h2bits(v.z, v.w);
        *(uint2*)&Ah[r * PA + c4] = u;
    }
    // fill B (W1), (k,k+1)-interleaved half2 pairs
    for (int i4 = tid; i4 < 64 * 64; i4 += 256) {
        int k2 = i4 >> 6, c4 = (i4 & 63) << 2;
        float4 v0 = *(const float4*)&W[(size_t)(2 * k2) * 256 + c4];
        float4 v1 = *(const float4*)&W[(size_t)(2 * k2 + 1) * 256 + c4];
        uint4 u;
        u.x = h2bits(v0.x, v1.x); u.y = h2bits(v0.y, v1.y);
        u.z = h2bits(v0.z, v1.z); u.w = h2bits(v0.w, v1.w);
        *(uint4*)&B2u[k2 * PB + c4] = u;
    }
    satt[tid] = att_s[tid];
    satt[256 + tid] = att_d[tid];
    __syncthreads();

    const int w = tid >> 5, lane = tid & 31;
    const int g = lane >> 2, t = lane & 3;
    const int wm = w & 1, wn = w >> 1;           // 2 x 4 warp grid
    const int rwarp = wm * 64;
    const int cwarp = wn * 64;

    float acc[4][8][4];
#pragma unroll
    for (int mt = 0; mt < 4; mt++)
#pragma unroll
        for (int n8 = 0; n8 < 8; n8++)
#pragma unroll
            for (int q = 0; q < 4; q++) acc[mt][n8][q] = 0.f;

    unsigned af0[4][4], bf0[8][2], af1[4][4], bf1[8][2];

    LOAD_FRAGS16(af0, bf0, 0);
#pragma unroll 1
    for (int kk = 0; kk < 8; kk += 2) {
        LOAD_FRAGS16(af1, bf1, kk + 1);
        MMA_FRAGS16(af0, bf0);
        if (kk + 2 < 8) LOAD_FRAGS16(af0, bf0, kk + 2);
        MMA_FRAGS16(af1, bf1);
    }

    // ---- fused score epilogue: this warp's 64 cols == head wn ----
#pragma unroll
    for (int mt = 0; mt < 4; mt++) {
        float ps0 = 0.f, pd0 = 0.f, ps1 = 0.f, pd1 = 0.f;
#pragma unroll
        for (int n8 = 0; n8 < 8; n8++) {
            int col = cwarp + n8 * 8 + 2 * t;
            float s0 = satt[col], s1 = satt[col + 1];
            float d0 = satt[256 + col], d1 = satt[256 + col + 1];
            ps0 += acc[mt][n8][0] * s0 + acc[mt][n8][1] * s1;
            pd0 += acc[mt][n8][0] * d0 + acc[mt][n8][1] * d1;
            ps1 += acc[mt][n8][2] * s0 + acc[mt][n8][3] * s1;
            pd1 += acc[mt][n8][2] * d0 + acc[mt][n8][3] * d1;
        }
#pragma unroll
        for (int o = 1; o <= 2; o <<= 1) {
            ps0 += __shfl_xor_sync(0xffffffffu, ps0, o);
            pd0 += __shfl_xor_sync(0xffffffffu, pd0, o);
            ps1 += __shfl_xor_sync(0xffffffffu, ps1, o);
            pd1 += __shfl_xor_sync(0xffffffffu, pd1, o);
        }
        int m0 = n0 + rwarp + mt * 16 + g;
        int m1 = m0 + 8;
        if (t == 0) {
            if (m0 < nN) { as_[(size_t)m0 * 4 + wn] = ps0; ad_[(size_t)m0 * 4 + wn] = pd0; }
            if (m1 < nN) { as_[(size_t)m1 * 4 + wn] = ps1; ad_[(size_t)m1 * 4 + wn] = pd1; }
        }
        bool w0 = (m0 < nN), w1 = (m1 < nN);
#pragma unroll
        for (int n8 = 0; n8 < 8; n8++) {
            int col = cwarp + n8 * 8 + 2 * t;
            if (w0) *(unsigned*)&Y[(size_t)m0 * 256 + col] = h2bits(acc[mt][n8][0], acc[mt][n8][1]);
            if (w1) *(unsigned*)&Y[(size_t)m1 * 256 + col] = h2bits(acc[mt][n8][2], acc[mt][n8][3]);
        }
    }
}

// ---------------- GEMM (FFMA2 path, used for layer2 + PQ): Y[N,M] = X[N,K] @ W[K,M] ----------------
template <int K, int M, int TN, int TH, int NSTEP, bool HALF_OUT, bool SC>
__launch_bounds__(TH, 1)
__global__ void gemm_xw(const float* __restrict__ X, const float* __restrict__ W,
                        void* __restrict__ Yv,
                        const float* __restrict__ att_s, const float* __restrict__ att_d,
                        float* __restrict__ as_, float* __restrict__ ad_, int nN) {
    extern __shared__ float sm[];
    constexpr int CG = M / 8;
    constexpr int PARTS = TH / CG;
    constexpr int NP = TN / PARTS;
    constexpr int HW = K * M / 2;
    static_assert(NP % NSTEP == 0, "NP % NSTEP");
    float* Xs = sm + K * M;
    const int tid = threadIdx.x;

    for (int i4 = tid; i4 < K * M / 4; i4 += TH) {
        int i = i4 * 4;
        int k = i / M, c = i % M;
        float4 v = *(const float4*)&W[i];
        int grp = (c >> 2) & 1;
        int d = (k * (M / 8) + (c >> 3)) * 4;
        *(float4*)&sm[(grp ? HW : 0) + d] = v;
    }
    const int n0 = blockIdx.x * TN;
    const int nn = min(TN, nN - n0);
    for (int i4 = tid; i4 < nn * K / 4; i4 += TH)
        ((float4*)Xs)[i4] = ((const float4*)(X + (size_t)n0 * K))[i4];
    __syncthreads();

    const int cg = tid % CG;
    const int part = tid / CG;
    const int nbase = part * NP;
    const ulonglong2* WA2 = (const ulonglong2*)sm;
    const ulonglong2* WB2 = (const ulonglong2*)(sm + HW);

    float4 avs0, avs1, avd0, avd1;
    if (SC) {
        avs0 = *(const float4*)&att_s[cg * 8];
        avs1 = *(const float4*)&att_s[cg * 8 + 4];
        avd0 = *(const float4*)&att_d[cg * 8];
        avd1 = *(const float4*)&att_d[cg * 8 + 4];
    }

    for (int nb = 0; nb < NP; nb += NSTEP) {
        ull a2[NSTEP][4];
#pragma unroll
        for (int j = 0; j < NSTEP; j++)
#pragma unroll
            for (int q = 0; q < 4; q++) a2[j][q] = 0ull;

#pragma unroll 2
        for (int k0 = 0; k0 < K; k0 += 4) {
            float4 xv[NSTEP];
#pragma unroll
            for (int j = 0; j < NSTEP; j++)
                xv[j] = *(const float4*)&Xs[(nbase + nb + j) * K + k0];
#pragma unroll
            for (int kk = 0; kk < 4; kk++) {
                ulonglong2 wA = WA2[(k0 + kk) * CG + cg];
                ulonglong2 wB = WB2[(k0 + kk) * CG + cg];
#pragma unroll
                for (int j = 0; j < NSTEP; j++) {
                    float xk = (kk == 0) ? xv[j].x : (kk == 1) ? xv[j].y
                             : (kk == 2) ? xv[j].z : xv[j].w;
                    ull xx = pack2(xk, xk);
                    a2[j][0] = ffma2(xx, wA.x, a2[j][0]);
                    a2[j][1] = ffma2(xx, wA.y, a2[j][1]);
                    a2[j][2] = ffma2(xx, wB.x, a2[j][2]);
                    a2[j][3] = ffma2(xx, wB.y, a2[j][3]);
                }
            }
        }
#pragma unroll
        for (int j = 0; j < NSTEP; j++) {
            int n = nbase + nb + j;
            float f0, f1, f2, f3, f4, f5, f6, f7;
            unpack2(a2[j][0], f0, f1); unpack2(a2[j][1], f2, f3);
            unpack2(a2[j][2], f4, f5); unpack2(a2[j][3], f6, f7);
            if (SC) {
                constexpr int C = M / 4;
                constexpr int RG = C / 8;
                float ps = f0 * avs0.x + f1 * avs0.y + f2 * avs0.z + f3 * avs0.w
                         + f4 * avs1.x + f5 * avs1.y + f6 * avs1.z + f7 * avs1.w;
                float pd = f0 * avd0.x + f1 * avd0.y + f2 * avd0.z + f3 * avd0.w
                         + f4 * avd1.x + f5 * avd1.y + f6 * avd1.z + f7 * avd1.w;
#pragma unroll
                for (int o = 1; o < RG; o <<= 1) {
                    ps += __shfl_xor_sync(0xffffffffu, ps, o);
                    pd += __shfl_xor_sync(0xffffffffu, pd, o);
                }
                if ((cg & (RG - 1)) == 0 && n < nn) {
                    int h = (cg * 8) / C;
                    as_[(size_t)(n0 + n) * 4 + h] = ps;
                    ad_[(size_t)(n0 + n) * 4 + h] = pd;
                }
            }
            if (n < nn) {
                if (HALF_OUT) {
                    uint4 o;
                    o.x = h2bits(f0, f1); o.y = h2bits(f2, f3);
                    o.z = h2bits(f4, f5); o.w = h2bits(f6, f7);
                    ((uint4*)Yv)[(size_t)(n0 + n) * (M / 8) + cg] = o;
                } else {
                    float* yp = (float*)Yv + (size_t)(n0 + n) * M + cg * 8;
                    *(ulonglong2*)yp = make_ulonglong2(pack2(f0, f1), pack2(f2, f3));
                    *(ulonglong2*)(yp + 4) = make_ulonglong2(pack2(f4, f5), pack2(f6, f7));
                }
            }
        }
    }
}

// ---- CSR aggregation C=64 (layer 1): 2x-unrolled loop, f32x2 accumulate ----
__launch_bounds__(256)
__global__ void agg_csr64(const int2* __restrict__ eid, const int* __restrict__ ptr,
                          const int* __restrict__ deg, const __half* __restrict__ xlh,
                          const float* __restrict__ as_, const float* __restrict__ ad_,
                          const float* __restrict__ bias, float* __restrict__ out) {
    int n = blockIdx.x * 8 + (threadIdx.x >> 5);
    if (n >= NN) return;
    int lane = threadIdx.x & 31;
    int h = lane >> 3;                    // head of this lane's 8 cols
    int p0 = ptr[n], dg = deg[n];
    float adh = ad_[(size_t)n * 4 + h];
    ull acc2[4];
#pragma unroll
    for (int i = 0; i < 4; i++) acc2[i] = 0ull;
    float den = 0.f;
    const uint4* xl4 = (const uint4*)xlh;   // 32 uint4 per row

    int j = 0;
    for (; j + 2 <= dg; j += 2) {
        int2 ea = eid[p0 + j];
        int2 eb = eid[p0 + j + 1];
        float ra = as_[(size_t)ea.y * 4 + h];
        float rb = as_[(size_t)eb.y * 4 + h];
        uint4 va = xl4[(size_t)ea.y * 32 + lane];
        uint4 vb = xl4[(size_t)eb.y * 32 + lane];
        float wa = leaky_exp(ra + adh);
        float wb = leaky_exp(rb + adh);
        den += wa + wb;
        ull wa2 = pack2(wa, wa), wb2 = pack2(wb, wb);
        const __half2* ha = (const __half2*)&va;
        const __half2* hb = (const __half2*)&vb;
#pragma unroll
        for (int i = 0; i < 4; i++) {
            float2 fa = __half22float2(ha[i]);
            float2 fb = __half22float2(hb[i]);
            acc2[i] = ffma2(pack2(fa.x, fa.y), wa2, acc2[i]);
            acc2[i] = ffma2(pack2(fb.x, fb.y), wb2, acc2[i]);
        }
    }
    if (j < dg) {
        int2 e = eid[p0 + j];
        float w = leaky_exp(as_[(size_t)e.y * 4 + h] + adh);
        den += w;
        uint4 v = xl4[(size_t)e.y * 32 + lane];
        ull ww = pack2(w, w);
        const __half2* hp = (const __half2*)&v;
#pragma unroll
        for (int i = 0; i < 4; i++) {
            float2 f = __half22float2(hp[i]);
            acc2[i] = ffma2(pack2(f.x, f.y), ww, acc2[i]);
        }
    }
    float acc[8];
#pragma unroll
    for (int i = 0; i < 4; i++) unpack2(acc2[i], acc[2 * i], acc[2 * i + 1]);
    float dh = 1.f / (den + 1e-16f);
#pragma unroll
    for (int i = 0; i < 8; i++) {
        acc[i] *= dh;
        acc[i] += __shfl_xor_sync(0xffffffffu, acc[i], 8);
        acc[i] += __shfl_xor_sync(0xffffffffu, acc[i], 16);
    }
    if (lane < 8) {
        float* op = out + (size_t)n * 64 + 8 * lane;
        const float* bp = bias + 8 * lane;
        float4 o0, o1;
        o0.x = 0.25f * acc[0] + bp[0]; o0.y = 0.25f * acc[1] + bp[1];
        o0.z = 0.25f * acc[2] + bp[2]; o0.w = 0.25f * acc[3] + bp[3];
        o1.x = 0.25f * acc[4] + bp[4]; o1.y = 0.25f * acc[5] + bp[5];
        o1.z = 0.25f * acc[6] + bp[6]; o1.w = 0.25f * acc[7] + bp[7];
        *(float4*)op = o0;
        *(float4*)(op + 4) = o1;
    }
}

// ---- CSR aggregation C=32 (layer 2): 2x-unrolled, f32x2; exports ex2/den2 ----
__launch_bounds__(256)
__global__ void agg_csr32(const int2* __restrict__ eid, const int* __restrict__ ptr,
                          const int* __restrict__ deg, const __half* __restrict__ xlh,
                          const float* __restrict__ as_, const float* __restrict__ ad_,
                          const float* __restrict__ bias, float* __restrict__ out,
                          float* __restrict__ ex2, float* __restrict__ den2) {
    int n = blockIdx.x * 8 + (threadIdx.x >> 5);
    if (n >= NN) return;
    int lane = threadIdx.x & 31;
    int h = lane >> 3;                    // head of this lane's 4 cols
    int p0 = ptr[n], dg = deg[n];
    float adh = ad_[(size_t)n * 4 + h];
    ull acc2[2];
    acc2[0] = 0ull; acc2[1] = 0ull;
    float den = 0.f;
    const uint2* xl2 = (const uint2*)xlh;   // 32 uint2 per row

    int j = 0;
    for (; j + 2 <= dg; j += 2) {
        int2 ea = eid[p0 + j];
        int2 eb = eid[p0 + j + 1];
        float ra = as_[(size_t)ea.y * 4 + h];
        float rb = as_[(size_t)eb.y * 4 + h];
        uint2 va = xl2[(size_t)ea.y * 32 + lane];
        uint2 vb = xl2[(size_t)eb.y * 32 + lane];
        float wa = leaky_exp(ra + adh);
        float wb = leaky_exp(rb + adh);
        den += wa + wb;
        if ((lane & 7) == 0) {
            ex2[(size_t)ea.x * 4 + h] = wa;
            ex2[(size_t)eb.x * 4 + h] = wb;
        }
        ull wa2 = pack2(wa, wa), wb2 = pack2(wb, wb);
        const __half2* ha = (const __half2*)&va;
        const __half2* hb = (const __half2*)&vb;
#pragma unroll
        for (int i = 0; i < 2; i++) {
            float2 fa = __half22float2(ha[i]);
            float2 fb = __half22float2(hb[i]);
            acc2[i] = ffma2(pack2(fa.x, fa.y), wa2, acc2[i]);
            acc2[i] = ffma2(pack2(fb.x, fb.y), wb2, acc2[i]);
        }
    }
    if (j < dg) {
        int2 e = eid[p0 + j];
        float w = leaky_exp(as_[(size_t)e.y * 4 + h] + adh);
        den += w;
        if ((lane & 7) == 0) ex2[(size_t)e.x * 4 + h] = w;
        uint2 v = xl2[(size_t)e.y * 32 + lane];
        ull ww = pack2(w, w);
        const __half2* hp = (const __half2*)&v;
#pragma unroll
        for (int i = 0; i < 2; i++) {
            float2 f = __half22float2(hp[i]);
            acc2[i] = ffma2(pack2(f.x, f.y), ww, acc2[i]);
        }
    }
    if ((lane & 7) == 0) den2[(size_t)n * 4 + h] = den;
    float acc[4];
    unpack2(acc2[0], acc[0], acc[1]);
    unpack2(acc2[1], acc[2], acc[3]);
    float dh = 1.f / (den + 1e-16f);
#pragma unroll
    for (int i = 0; i < 4; i++) {
        acc[i] *= dh;
        acc[i] += __shfl_xor_sync(0xffffffffu, acc[i], 8);
        acc[i] += __shfl_xor_sync(0xffffffffu, acc[i], 16);
    }
    if (lane < 8) {
        const float* bp = bias + 4 * lane;
        float4 o;
        o.x = 0.25f * acc[0] + bp[0]; o.y = 0.25f * acc[1] + bp[1];
        o.z = 0.25f * acc[2] + bp[2]; o.w = 0.25f * acc[3] + bp[3];
        *(float4*)(out + (size_t)n * 32 + 4 * lane) = o;
    }
}

// ---------------- edge MLP (decomposed, fp16 P/Q, f32x2 hidden): relu(P[s]+Q[d]+alpha@B+b1) @ W2 ----------------
__launch_bounds__(256)
__global__ void edge_mlp2_kernel(const int* __restrict__ src, const int* __restrict__ dst,
                                 const __half* __restrict__ PQ,
                                 const float* __restrict__ ex2, const float* __restrict__ den2,
                                 const float* __restrict__ mW1, const float* __restrict__ mb1,
                                 const float* __restrict__ mW2, const float* __restrict__ mb2,
                                 float* __restrict__ eo) {
    __shared__ __align__(8) float W1B[4 * 64];   // rows 32..35 of mW1 (alpha part)
    __shared__ __align__(8) float B1[64];
    __shared__ ull W2p[64];         // (W2[j][0], W2[j][1]) pairs
    __shared__ float B2[2];
    int tid = threadIdx.x;
    for (int i = tid; i < 256; i += 256) W1B[i] = mW1[32 * 64 + i];
    if (tid < 64) B1[tid] = mb1[tid];
    if (tid < 128) ((float*)W2p)[tid] = mW2[tid];
    if (tid < 2) B2[tid] = mb2[tid];
    __syncthreads();

    int e = blockIdx.x * 256 + tid;
    if (e >= EE) return;
    int s = src[e], d = dst[e];

    float4 a4 = *(const float4*)(ex2 + (size_t)e * 4);
    float4 dn = *(const float4*)(den2 + (size_t)d * 4);
    ull al0_2, al1_2, al2_2, al3_2;
    {
        float al0 = a4.x / (dn.x + 1e-16f);
        float al1 = a4.y / (dn.y + 1e-16f);
        float al2 = a4.z / (dn.z + 1e-16f);
        float al3 = a4.w / (dn.w + 1e-16f);
        al0_2 = pack2(al0, al0); al1_2 = pack2(al1, al1);
        al2_2 = pack2(al2, al2); al3_2 = pack2(al3, al3);
    }

    const ull* B1p = (const ull*)B1;       // pair j2 = (B1[2j2], B1[2j2+1])
    const ull* W1Bp = (const ull*)W1B;     // row h at W1Bp[h*32 + j2]

    const uint4* PQh = (const uint4*)PQ;  // 16 uint4 per node row (128 halves)
    size_t bs = (size_t)s * 16;           // P: cols 0..63  -> uint4 idx 0..7
    size_t bd = (size_t)d * 16 + 8;       // Q: cols 64..127 -> uint4 idx 0..7

    ull o2 = pack2(B2[0], B2[1]);
#pragma unroll
    for (int qq = 0; qq < 8; qq++) {
        uint4 ph = PQh[bs + qq];
        uint4 qh = PQh[bd + qq];
        const __half2* php = (const __half2*)&ph;
        const __half2* qhp = (const __half2*)&qh;
#pragma unroll
        for (int u2 = 0; u2 < 4; u2++) {
            int j2 = qq * 4 + u2;          // hidden pair 0..31
            float2 pf = __half22float2(php[u2]);
            float2 qf = __half22float2(qhp[u2]);
            ull hv2 = add2(pack2(pf.x + qf.x, pf.y + qf.y), B1p[j2]);
            hv2 = ffma2(al0_2, W1Bp[j2], hv2);
            hv2 = ffma2(al1_2, W1Bp[32 + j2], hv2);
            hv2 = ffma2(al2_2, W1Bp[64 + j2], hv2);
            hv2 = ffma2(al3_2, W1Bp[96 + j2], hv2);
            float h0, h1;
            unpack2(hv2, h0, h1);
            h0 = fmaxf(h0, 0.f); h1 = fmaxf(h1, 0.f);
            o2 = ffma2(pack2(h0, h0), W2p[2 * j2], o2);
            o2 = ffma2(pack2(h1, h1), W2p[2 * j2 + 1], o2);
        }
    }
    float o0, o1;
    unpack2(o2, o0, o1);
    ((float2*)eo)[e] = make_float2(o0, o1);
}

// ---------------- launch ----------------
extern "C" void kernel_launch(void* const* d_in, const int* in_sizes, int n_in,
                              void* d_out, int out_size) {
    const float* x    = (const float*)d_in[0];
    const int*   ei   = (const int*)d_in[1];
    const float* W1   = (const float*)d_in[4];
    const float* a1s  = (const float*)d_in[5];
    const float* a1d  = (const float*)d_in[6];
    const float* b1   = (const float*)d_in[7];
    const float* W3   = (const float*)d_in[8];
    const float* a3s  = (const float*)d_in[9];
    const float* a3d  = (const float*)d_in[10];
    const float* b3   = (const float*)d_in[11];
    const float* mW1  = (const float*)d_in[12];
    const float* mb1  = (const float*)d_in[13];
    const float* mW2  = (const float*)d_in[14];
    const float* mb2  = (const float*)d_in[15];

    const int* src = ei;
    const int* dst = ei + EE;

    float* out_nodes = (float*)d_out;             // N*32
    float* out_edges = (float*)d_out + NN * 32;   // E*2

    __half *p_xl1h, *p_xl2h, *p_pqh;
    float *p_x2, *p_a1s, *p_a1d, *p_a2s, *p_a2d, *p_ex2;
    float *p_den2, *p_wpq;
    int *p_deg, *p_ptr, *p_pos, *p_bsum;
    int2 *p_eid;
    cudaGetSymbolAddress((void**)&p_xl1h, g_xl1h);
    cudaGetSymbolAddress((void**)&p_xl2h, g_xl2h);
    cudaGetSymbolAddress((void**)&p_x2,  g_x2);
    cudaGetSymbolAddress((void**)&p_a1s, g_a1s);
    cudaGetSymbolAddress((void**)&p_a1d, g_a1d);
    cudaGetSymbolAddress((void**)&p_a2s, g_a2s);
    cudaGetSymbolAddress((void**)&p_a2d, g_a2d);
    cudaGetSymbolAddress((void**)&p_ex2, g_ex2);
    cudaGetSymbolAddress((void**)&p_den2, g_den2);
    cudaGetSymbolAddress((void**)&p_pqh, g_pqh);
    cudaGetSymbolAddress((void**)&p_wpq, g_wpq);
    cudaGetSymbolAddress((void**)&p_deg, g_deg);
    cudaGetSymbolAddress((void**)&p_ptr, g_ptr);
    cudaGetSymbolAddress((void**)&p_pos, g_pos);
    cudaGetSymbolAddress((void**)&p_bsum, g_bsum);
    cudaGetSymbolAddress((void**)&p_eid, g_eid);

    static cudaStream_t s2 = nullptr;
    static cudaEvent_t evFork = nullptr, evJoin = nullptr;
    if (!s2) {
        cudaStreamCreateWithFlags(&s2, cudaStreamNonBlocking);
        cudaEventCreateWithFlags(&evFork, cudaEventDisableTiming);
        cudaEventCreateWithFlags(&evJoin, cudaEventDisableTiming);
    }

    const int NB = (NN + 511) / 512;  // 98
    const int SMEM1 = (8704 + 16896 + 512) * 4;  // 104448 B

    cudaMemsetAsync(p_deg, 0, (size_t)NN * 4);
    cudaEventRecord(evFork, 0);                       // fork point
    cudaStreamWaitEvent(s2, evFork, 0);

    // main stream: CSR build chain
    hist_kernel<<<(EE + 255) / 256, 256>>>(dst, p_deg);
    scanA_kernel<<<NB, 512>>>(p_deg, p_ptr, p_bsum);
    scanB_kernel<<<1, 128>>>(p_bsum, NB);

    // side stream: gemm1 fp16-mma + repack
    cudaFuncSetAttribute((const void*)gemm1_f16,
                         cudaFuncAttributeMaxDynamicSharedMemorySize, SMEM1);
    gemm1_f16<<<(NN + 127) / 128, 256, SMEM1, s2>>>(
        x, W1, p_xl1h, a1s, a1d, p_a1s, p_a1d, NN);
    repack_wpq<<<(32 * 128 + 255) / 256, 256, 0, s2>>>(mW1, p_wpq);
    cudaEventRecord(evJoin, s2);

    scanC_kernel<<<NB, 512>>>(p_ptr, p_bsum, p_pos);
    scatter_kernel<<<(EE + 255) / 256, 256>>>(src, dst, p_pos, p_eid);

    cudaStreamWaitEvent(0, evJoin, 0);                // join

    // Layer 1 aggregation (fused exp/den/finalize)
    agg_csr64<<<(NN + 7) / 8, 256>>>(p_eid, p_ptr, p_deg, p_xl1h,
                                     p_a1s, p_a1d, b1, p_x2);

    // Layer 2
    cudaFuncSetAttribute((const void*)gemm_xw<64, 128, 128, 256, 8, true, true>,
                         cudaFuncAttributeMaxDynamicSharedMemorySize, 65536);
    gemm_xw<64, 128, 128, 256, 8, true, true><<<(NN + 127) / 128, 256, 65536>>>(
        p_x2, W3, p_xl2h, a3s, a3d, p_a2s, p_a2d, NN);
    agg_csr32<<<(NN + 7) / 8, 256>>>(p_eid, p_ptr, p_deg, p_xl2h,
                                     p_a2s, p_a2d, b3, out_nodes,
                                     p_ex2, p_den2);

    // Edge MLP: per-node P/Q precompute (fp16 out), then light per-edge kernel
    cudaFuncSetAttribute((const void*)gemm_xw<32, 128, 128, 256, 8, true, false>,
                         cudaFuncAttributeMaxDynamicSharedMemorySize, 32768);
    gemm_xw<32, 128, 128, 256, 8, true, false><<<(NN + 127) / 128, 256, 32768>>>(
        out_nodes, p_wpq, p_pqh, nullptr, nullptr, nullptr, nullptr, NN);
    edge_mlp2_kernel<<<(EE + 255) / 256, 256>>>(src, dst, p_pqh, p_ex2, p_den2,
                                                mW1, mb1, mW2, mb2, out_edges);
}

// round 17
// speedup vs baseline: 1.1665x; 1.0503x over previous
#include <cuda_runtime.h>
#include <cuda_fp16.h>
#include <cuda_bf16.h>

#define NN 50000
#define EE 800000
#define HH 4

typedef unsigned long long ull;

// ---------------- scratch ----------------
__device__ __align__(16) __half g_xh[50048 * 128];      // X in fp16 (padded rows)
__device__ __align__(16) __half2 g_w1h[64 * 256];       // W1 (k,k+1)-interleaved half2
__device__ __align__(16) __half g_xl1h[NN * 256];
__device__ __align__(16) __half g_xl2h[NN * 128];
__device__ __align__(16) float g_a1s[NN * 4];
__device__ __align__(16) float g_a1d[NN * 4];
__device__ __align__(16) float g_x2[NN * 64];
__device__ __align__(16) float g_a2s[NN * 4];
__device__ __align__(16) float g_a2d[NN * 4];
__device__ __align__(16) float g_ex2[EE * 4];
__device__ __align__(16) float g_den2[NN * 4];
__device__ __align__(16) __half g_pqh[NN * 128];
__device__ __align__(16) float g_wpq[32 * 128];
__device__ int  g_deg[NN];
__device__ int  g_ptr[NN];
__device__ int  g_pos[NN];
__device__ int  g_bsum[128];
__device__ __align__(8) int2 g_eid[EE];

__device__ __forceinline__ ull ffma2(ull a, ull b, ull c) {
    ull d;
    asm("fma.rn.f32x2 %0, %1, %2, %3;" : "=l"(d) : "l"(a), "l"(b), "l"(c));
    return d;
}
__device__ __forceinline__ ull add2(ull a, ull b) {
    ull d;
    asm("add.rn.f32x2 %0, %1, %2;" : "=l"(d) : "l"(a), "l"(b));
    return d;
}
__device__ __forceinline__ ull pack2(float x, float y) {
    ull d; asm("mov.b64 %0, {%1, %2};" : "=l"(d) : "f"(x), "f"(y)); return d;
}
__device__ __forceinline__ void unpack2(ull v, float& x, float& y) {
    asm("mov.b64 {%0, %1}, %2;" : "=f"(x), "=f"(y) : "l"(v));
}
__device__ __forceinline__ unsigned h2bits(float a, float b) {
    __half2 h = __floats2half2_rn(a, b);
    return *reinterpret_cast<unsigned*>(&h);
}
__device__ __forceinline__ float leaky_exp(float t) {
    t = fmaxf(t, 0.f) + 0.2f * fminf(t, 0.f);
    return __expf(t);
}

// ---------------- operand pre-conversion for gemm1 ----------------
__global__ void conv_x(const float* __restrict__ X, __half* __restrict__ Xh) {
    int i8 = blockIdx.x * blockDim.x + threadIdx.x;   // 8 halves per thread
    if (i8 >= NN * 16) return;
    const float4* xp = (const float4*)X + (size_t)i8 * 2;
    float4 a = xp[0], b = xp[1];
    uint4 u;
    u.x = h2bits(a.x, a.y); u.y = h2bits(a.z, a.w);
    u.z = h2bits(b.x, b.y); u.w = h2bits(b.z, b.w);
    ((uint4*)Xh)[i8] = u;
}
__global__ void conv_w1(const float* __restrict__ W, __half2* __restrict__ Wh) {
    int i4 = blockIdx.x * blockDim.x + threadIdx.x;   // 4 half2 per thread
    if (i4 >= 64 * 64) return;
    int k2 = i4 >> 6, c4 = (i4 & 63) << 2;
    float4 v0 = *(const float4*)&W[(size_t)(2 * k2) * 256 + c4];
    float4 v1 = *(const float4*)&W[(size_t)(2 * k2 + 1) * 256 + c4];
    uint4 u;
    u.x = h2bits(v0.x, v1.x); u.y = h2bits(v0.y, v1.y);
    u.z = h2bits(v0.z, v1.z); u.w = h2bits(v0.w, v1.w);
    ((uint4*)Wh)[i4] = u;
}

// ---------------- CSR build ----------------
__global__ void hist_kernel(const int* __restrict__ dst, int* __restrict__ deg) {
    int e = blockIdx.x * blockDim.x + threadIdx.x;
    if (e < EE) atomicAdd(&deg[dst[e]], 1);
}
__global__ void scanA_kernel(const int* __restrict__ deg, int* __restrict__ out,
                             int* __restrict__ bsum) {
    __shared__ int sm[512];
    int t = threadIdx.x;
    int g = blockIdx.x * 512 + t;
    int v = (g < NN) ? deg[g] : 0;
    sm[t] = v; __syncthreads();
    for (int o = 1; o < 512; o <<= 1) {
        int tt = (t >= o) ? sm[t - o] : 0;
        __syncthreads();
        sm[t] += tt;
        __syncthreads();
    }
    if (g < NN) out[g] = sm[t] - v;            // exclusive
    if (t == 511) bsum[blockIdx.x] = sm[511];
}
__global__ void scanB_kernel(int* __restrict__ bsum, int nb) {
    __shared__ int sm[128];
    int t = threadIdx.x;
    int v = (t < nb) ? bsum[t] : 0;
    sm[t] = v; __syncthreads();
    for (int o = 1; o < 128; o <<= 1) {
        int tt = (t >= o) ? sm[t - o] : 0;
        __syncthreads();
        sm[t] += tt;
        __syncthreads();
    }
    if (t < nb) bsum[t] = sm[t] - v;           // exclusive
}
__global__ void scanC_kernel(int* __restrict__ ptr, const int* __restrict__ bsum,
                             int* __restrict__ pos) {
    int g = blockIdx.x * 512 + threadIdx.x;
    if (g < NN) {
        int v = ptr[g] + bsum[blockIdx.x];
        ptr[g] = v;
        pos[g] = v;
    }
}
__global__ void scatter_kernel(const int* __restrict__ src, const int* __restrict__ dst,
                               int* __restrict__ pos, int2* __restrict__ eid) {
    int e = blockIdx.x * blockDim.x + threadIdx.x;
    if (e < EE) {
        int p = atomicAdd(&pos[dst[e]], 1);
        eid[p] = make_int2(e, src[e]);
    }
}

// -------- repack mW1 rows {0..31}->cols 0..63, rows {36..67}->cols 64..127 --------
__global__ void repack_wpq(const float* __restrict__ mW1, float* __restrict__ wpq) {
    int idx = blockIdx.x * blockDim.x + threadIdx.x;
    if (idx >= 32 * 128) return;
    int k = idx / 128, j = idx % 128;
    wpq[idx] = (j < 64) ? mW1[k * 64 + j] : mW1[(36 + k) * 64 + (j - 64)];
}

// ---------------- gemm1 via fp16 mma.sync m16n8k16 (preconverted operands) ----------------
// 8 warps = 2(m) x 4(n), warp tile 64x64. 8 k16-steps, double-buffered frags.
#define PA 136
#define PB 264

#define LOAD_FRAGS16(AF, BF, KK)                                            \
    do {                                                                    \
        int _kh = (KK) * 16 + 2 * t;                                        \
        _Pragma("unroll")                                                   \
        for (int mt = 0; mt < 4; mt++) {                                    \
            const __half* ar = &Ah[(rwarp + mt * 16 + g) * PA + _kh];       \
            AF[mt][0] = *(const unsigned*)(ar);                             \
            AF[mt][1] = *(const unsigned*)(ar + 8 * PA);                    \
            AF[mt][2] = *(const unsigned*)(ar + 8);                         \
            AF[mt][3] = *(const unsigned*)(ar + 8 * PA + 8);                \
        }                                                                   \
        const unsigned* br = &B2u[((KK) * 8 + t) * PB + cwarp + g];         \
        _Pragma("unroll")                                                   \
        for (int n8 = 0; n8 < 8; n8++) {                                    \
            BF[n8][0] = br[n8 * 8];                                         \
            BF[n8][1] = br[4 * PB + n8 * 8];                                \
        }                                                                   \
    } while (0)

#define MMA_FRAGS16(AF, BF)                                                 \
    do {                                                                    \
        _Pragma("unroll")                                                   \
        for (int n8 = 0; n8 < 8; n8++)                                      \
            _Pragma("unroll")                                               \
            for (int mt = 0; mt < 4; mt++) {                                \
                asm volatile(                                               \
                    "mma.sync.aligned.m16n8k16.row.col.f32.f16.f16.f32 "   \
                    "{%0,%1,%2,%3}, {%4,%5,%6,%7}, {%8,%9}, {%0,%1,%2,%3};" \
                    : "+f"(acc[mt][n8][0]), "+f"(acc[mt][n8][1]),           \
                      "+f"(acc[mt][n8][2]), "+f"(acc[mt][n8][3])            \
                    : "r"(AF[mt][0]), "r"(AF[mt][1]),                       \
                      "r"(AF[mt][2]), "r"(AF[mt][3]),                       \
                      "r"(BF[n8][0]), "r"(BF[n8][1]));                      \
            }                                                               \
    } while (0)

__global__ __launch_bounds__(256, 1)
void gemm1_f16(const __half* __restrict__ Xh, const __half2* __restrict__ Wh,
               __half* __restrict__ Y,
               const float* __restrict__ att_s, const float* __restrict__ att_d,
               float* __restrict__ as_, float* __restrict__ ad_, int nN) {
    extern __shared__ float sm[];
    __half* Ah = (__half*)sm;               // 128 x PA halves (34816 B = 8704 floats)
    unsigned* B2u = (unsigned*)(sm + 8704); // 64 x PB half2 (67584 B = 16896 floats)
    float* satt = sm + 8704 + 16896;        // [0:256) att_s, [256:512) att_d
    const int tid = threadIdx.x;
    const int n0 = blockIdx.x * 128;
    const int nn = min(128, nN - n0);

    // fill A: pure 16B copies from preconverted Xh (rows >= nn read in-bounds of padded g_xh)
    for (int i8 = tid; i8 < 128 * 16; i8 += 256) {
        int r = i8 >> 4, c8 = (i8 & 15) << 3;
        uint4 u = *(const uint4*)&Xh[(size_t)(n0 + r) * 128 + c8];
        *(uint4*)&Ah[r * PA + c8] = u;
    }
    // fill B: pure 16B copies from preconverted Wh
    for (int i4 = tid; i4 < 64 * 64; i4 += 256) {
        int k2 = i4 >> 6, c4 = (i4 & 63) << 2;
        uint4 u = ((const uint4*)Wh)[i4];
        *(uint4*)&B2u[k2 * PB + c4] = u;
    }
    satt[tid] = att_s[tid];
    satt[256 + tid] = att_d[tid];
    __syncthreads();

    const int w = tid >> 5, lane = tid & 31;
    const int g = lane >> 2, t = lane & 3;
    const int wm = w & 1, wn = w >> 1;           // 2 x 4 warp grid
    const int rwarp = wm * 64;
    const int cwarp = wn * 64;

    float acc[4][8][4];
#pragma unroll
    for (int mt = 0; mt < 4; mt++)
#pragma unroll
        for (int n8 = 0; n8 < 8; n8++)
#pragma unroll
            for (int q = 0; q < 4; q++) acc[mt][n8][q] = 0.f;

    unsigned af0[4][4], bf0[8][2], af1[4][4], bf1[8][2];

    LOAD_FRAGS16(af0, bf0, 0);
#pragma unroll 1
    for (int kk = 0; kk < 8; kk += 2) {
        LOAD_FRAGS16(af1, bf1, kk + 1);
        MMA_FRAGS16(af0, bf0);
        if (kk + 2 < 8) LOAD_FRAGS16(af0, bf0, kk + 2);
        MMA_FRAGS16(af1, bf1);
    }

    // ---- fused score epilogue: this warp's 64 cols == head wn ----
#pragma unroll
    for (int mt = 0; mt < 4; mt++) {
        float ps0 = 0.f, pd0 = 0.f, ps1 = 0.f, pd1 = 0.f;
#pragma unroll
        for (int n8 = 0; n8 < 8; n8++) {
            int col = cwarp + n8 * 8 + 2 * t;
            float s0 = satt[col], s1 = satt[col + 1];
            float d0 = satt[256 + col], d1 = satt[256 + col + 1];
            ps0 += acc[mt][n8][0] * s0 + acc[mt][n8][1] * s1;
            pd0 += acc[mt][n8][0] * d0 + acc[mt][n8][1] * d1;
            ps1 += acc[mt][n8][2] * s0 + acc[mt][n8][3] * s1;
            pd1 += acc[mt][n8][2] * d0 + acc[mt][n8][3] * d1;
        }
#pragma unroll
        for (int o = 1; o <= 2; o <<= 1) {
            ps0 += __shfl_xor_sync(0xffffffffu, ps0, o);
            pd0 += __shfl_xor_sync(0xffffffffu, pd0, o);
            ps1 += __shfl_xor_sync(0xffffffffu, ps1, o);
            pd1 += __shfl_xor_sync(0xffffffffu, pd1, o);
        }
        int m0 = n0 + rwarp + mt * 16 + g;
        int m1 = m0 + 8;
        if (t == 0) {
            if (m0 < nN) { as_[(size_t)m0 * 4 + wn] = ps0; ad_[(size_t)m0 * 4 + wn] = pd0; }
            if (m1 < nN) { as_[(size_t)m1 * 4 + wn] = ps1; ad_[(size_t)m1 * 4 + wn] = pd1; }
        }
        bool w0 = (m0 < nN), w1 = (m1 < nN);
#pragma unroll
        for (int n8 = 0; n8 < 8; n8++) {
            int col = cwarp + n8 * 8 + 2 * t;
            if (w0) *(unsigned*)&Y[(size_t)m0 * 256 + col] = h2bits(acc[mt][n8][0], acc[mt][n8][1]);
            if (w1) *(unsigned*)&Y[(size_t)m1 * 256 + col] = h2bits(acc[mt][n8][2], acc[mt][n8][3]);
        }
    }
}

// ---------------- GEMM (FFMA2 path, used for layer2 + PQ): Y[N,M] = X[N,K] @ W[K,M] ----------------
template <int K, int M, int TN, int TH, int NSTEP, bool HALF_OUT, bool SC>
__launch_bounds__(TH, 1)
__global__ void gemm_xw(const float* __restrict__ X, const float* __restrict__ W,
                        void* __restrict__ Yv,
                        const float* __restrict__ att_s, const float* __restrict__ att_d,
                        float* __restrict__ as_, float* __restrict__ ad_, int nN) {
    extern __shared__ float sm[];
    constexpr int CG = M / 8;
    constexpr int PARTS = TH / CG;
    constexpr int NP = TN / PARTS;
    constexpr int HW = K * M / 2;
    static_assert(NP % NSTEP == 0, "NP % NSTEP");
    float* Xs = sm + K * M;
    const int tid = threadIdx.x;

    for (int i4 = tid; i4 < K * M / 4; i4 += TH) {
        int i = i4 * 4;
        int k = i / M, c = i % M;
        float4 v = *(const float4*)&W[i];
        int grp = (c >> 2) & 1;
        int d = (k * (M / 8) + (c >> 3)) * 4;
        *(float4*)&sm[(grp ? HW : 0) + d] = v;
    }
    const int n0 = blockIdx.x * TN;
    const int nn = min(TN, nN - n0);
    for (int i4 = tid; i4 < nn * K / 4; i4 += TH)
        ((float4*)Xs)[i4] = ((const float4*)(X + (size_t)n0 * K))[i4];
    __syncthreads();

    const int cg = tid % CG;
    const int part = tid / CG;
    const int nbase = part * NP;
    const ulonglong2* WA2 = (const ulonglong2*)sm;
    const ulonglong2* WB2 = (const ulonglong2*)(sm + HW);

    float4 avs0, avs1, avd0, avd1;
    if (SC) {
        avs0 = *(const float4*)&att_s[cg * 8];
        avs1 = *(const float4*)&att_s[cg * 8 + 4];
        avd0 = *(const float4*)&att_d[cg * 8];
        avd1 = *(const float4*)&att_d[cg * 8 + 4];
    }

    for (int nb = 0; nb < NP; nb += NSTEP) {
        ull a2[NSTEP][4];
#pragma unroll
        for (int j = 0; j < NSTEP; j++)
#pragma unroll
            for (int q = 0; q < 4; q++) a2[j][q] = 0ull;

#pragma unroll 2
        for (int k0 = 0; k0 < K; k0 += 4) {
            float4 xv[NSTEP];
#pragma unroll
            for (int j = 0; j < NSTEP; j++)
                xv[j] = *(const float4*)&Xs[(nbase + nb + j) * K + k0];
#pragma unroll
            for (int kk = 0; kk < 4; kk++) {
                ulonglong2 wA = WA2[(k0 + kk) * CG + cg];
                ulonglong2 wB = WB2[(k0 + kk) * CG + cg];
#pragma unroll
                for (int j = 0; j < NSTEP; j++) {
                    float xk = (kk == 0) ? xv[j].x : (kk == 1) ? xv[j].y
                             : (kk == 2) ? xv[j].z : xv[j].w;
                    ull xx = pack2(xk, xk);
                    a2[j][0] = ffma2(xx, wA.x, a2[j][0]);
                    a2[j][1] = ffma2(xx, wA.y, a2[j][1]);
                    a2[j][2] = ffma2(xx, wB.x, a2[j][2]);
                    a2[j][3] = ffma2(xx, wB.y, a2[j][3]);
                }
            }
        }
#pragma unroll
        for (int j = 0; j < NSTEP; j++) {
            int n = nbase + nb + j;
            float f0, f1, f2, f3, f4, f5, f6, f7;
            unpack2(a2[j][0], f0, f1); unpack2(a2[j][1], f2, f3);
            unpack2(a2[j][2], f4, f5); unpack2(a2[j][3], f6, f7);
            if (SC) {
                constexpr int C = M / 4;
                constexpr int RG = C / 8;
                float ps = f0 * avs0.x + f1 * avs0.y + f2 * avs0.z + f3 * avs0.w
                         + f4 * avs1.x + f5 * avs1.y + f6 * avs1.z + f7 * avs1.w;
                float pd = f0 * avd0.x + f1 * avd0.y + f2 * avd0.z + f3 * avd0.w
                         + f4 * avd1.x + f5 * avd1.y + f6 * avd1.z + f7 * avd1.w;
#pragma unroll
                for (int o = 1; o < RG; o <<= 1) {
                    ps += __shfl_xor_sync(0xffffffffu, ps, o);
                    pd += __shfl_xor_sync(0xffffffffu, pd, o);
                }
                if ((cg & (RG - 1)) == 0 && n < nn) {
                    int h = (cg * 8) / C;
                    as_[(size_t)(n0 + n) * 4 + h] = ps;
                    ad_[(size_t)(n0 + n) * 4 + h] = pd;
                }
            }
            if (n < nn) {
                if (HALF_OUT) {
                    uint4 o;
                    o.x = h2bits(f0, f1); o.y = h2bits(f2, f3);
                    o.z = h2bits(f4, f5); o.w = h2bits(f6, f7);
                    ((uint4*)Yv)[(size_t)(n0 + n) * (M / 8) + cg] = o;
                } else {
                    float* yp = (float*)Yv + (size_t)(n0 + n) * M + cg * 8;
                    *(ulonglong2*)yp = make_ulonglong2(pack2(f0, f1), pack2(f2, f3));
                    *(ulonglong2*)(yp + 4) = make_ulonglong2(pack2(f4, f5), pack2(f6, f7));
                }
            }
        }
    }
}

// ---- CSR aggregation C=64 (layer 1): 2x-unrolled loop, f32x2 accumulate ----
__launch_bounds__(256)
__global__ void agg_csr64(const int2* __restrict__ eid, const int* __restrict__ ptr,
                          const int* __restrict__ deg, const __half* __restrict__ xlh,
                          const float* __restrict__ as_, const float* __restrict__ ad_,
                          const float* __restrict__ bias, float* __restrict__ out) {
    int n = blockIdx.x * 8 + (threadIdx.x >> 5);
    if (n >= NN) return;
    int lane = threadIdx.x & 31;
    int h = lane >> 3;                    // head of this lane's 8 cols
    int p0 = ptr[n], dg = deg[n];
    float adh = ad_[(size_t)n * 4 + h];
    ull acc2[4];
#pragma unroll
    for (int i = 0; i < 4; i++) acc2[i] = 0ull;
    float den = 0.f;
    const uint4* xl4 = (const uint4*)xlh;   // 32 uint4 per row

    int j = 0;
    for (; j + 2 <= dg; j += 2) {
        int2 ea = eid[p0 + j];
        int2 eb = eid[p0 + j + 1];
        float ra = as_[(size_t)ea.y * 4 + h];
        float rb = as_[(size_t)eb.y * 4 + h];
        uint4 va = xl4[(size_t)ea.y * 32 + lane];
        uint4 vb = xl4[(size_t)eb.y * 32 + lane];
        float wa = leaky_exp(ra + adh);
        float wb = leaky_exp(rb + adh);
        den += wa + wb;
        ull wa2 = pack2(wa, wa), wb2 = pack2(wb, wb);
        const __half2* ha = (const __half2*)&va;
        const __half2* hb = (const __half2*)&vb;
#pragma unroll
        for (int i = 0; i < 4; i++) {
            float2 fa = __half22float2(ha[i]);
            float2 fb = __half22float2(hb[i]);
            acc2[i] = ffma2(pack2(fa.x, fa.y), wa2, acc2[i]);
            acc2[i] = ffma2(pack2(fb.x, fb.y), wb2, acc2[i]);
        }
    }
    if (j < dg) {
        int2 e = eid[p0 + j];
        float w = leaky_exp(as_[(size_t)e.y * 4 + h] + adh);
        den += w;
        uint4 v = xl4[(size_t)e.y * 32 + lane];
        ull ww = pack2(w, w);
        const __half2* hp = (const __half2*)&v;
#pragma unroll
        for (int i = 0; i < 4; i++) {
            float2 f = __half22float2(hp[i]);
            acc2[i] = ffma2(pack2(f.x, f.y), ww, acc2[i]);
        }
    }
    float acc[8];
#pragma unroll
    for (int i = 0; i < 4; i++) unpack2(acc2[i], acc[2 * i], acc[2 * i + 1]);
    float dh = 1.f / (den + 1e-16f);
#pragma unroll
    for (int i = 0; i < 8; i++) {
        acc[i] *= dh;
        acc[i] += __shfl_xor_sync(0xffffffffu, acc[i], 8);
        acc[i] += __shfl_xor_sync(0xffffffffu, acc[i], 16);
    }
    if (lane < 8) {
        float* op = out + (size_t)n * 64 + 8 * lane;
        const float* bp = bias + 8 * lane;
        float4 o0, o1;
        o0.x = 0.25f * acc[0] + bp[0]; o0.y = 0.25f * acc[1] + bp[1];
        o0.z = 0.25f * acc[2] + bp[2]; o0.w = 0.25f * acc[3] + bp[3];
        o1.x = 0.25f * acc[4] + bp[4]; o1.y = 0.25f * acc[5] + bp[5];
        o1.z = 0.25f * acc[6] + bp[6]; o1.w = 0.25f * acc[7] + bp[7];
        *(float4*)op = o0;
        *(float4*)(op + 4) = o1;
    }
}

// ---- CSR aggregation C=32 (layer 2): 2x-unrolled, f32x2; exports ex2/den2 ----
__launch_bounds__(256)
__global__ void agg_csr32(const int2* __restrict__ eid, const int* __restrict__ ptr,
                          const int* __restrict__ deg, const __half* __restrict__ xlh,
                          const float* __restrict__ as_, const float* __restrict__ ad_,
                          const float* __restrict__ bias, float* __restrict__ out,
                          float* __restrict__ ex2, float* __restrict__ den2) {
    int n = blockIdx.x * 8 + (threadIdx.x >> 5);
    if (n >= NN) return;
    int lane = threadIdx.x & 31;
    int h = lane >> 3;                    // head of this lane's 4 cols
    int p0 = ptr[n], dg = deg[n];
    float adh = ad_[(size_t)n * 4 + h];
    ull acc2[2];
    acc2[0] = 0ull; acc2[1] = 0ull;
    float den = 0.f;
    const uint2* xl2 = (const uint2*)xlh;   // 32 uint2 per row

    int j = 0;
    for (; j + 2 <= dg; j += 2) {
        int2 ea = eid[p0 + j];
        int2 eb = eid[p0 + j + 1];
        float ra = as_[(size_t)ea.y * 4 + h];
        float rb = as_[(size_t)eb.y * 4 + h];
        uint2 va = xl2[(size_t)ea.y * 32 + lane];
        uint2 vb = xl2[(size_t)eb.y * 32 + lane];
        float wa = leaky_exp(ra + adh);
        float wb = leaky_exp(rb + adh);
        den += wa + wb;
        if ((lane & 7) == 0) {
            ex2[(size_t)ea.x * 4 + h] = wa;
            ex2[(size_t)eb.x * 4 + h] = wb;
        }
        ull wa2 = pack2(wa, wa), wb2 = pack2(wb, wb);
        const __half2* ha = (const __half2*)&va;
        const __half2* hb = (const __half2*)&vb;
#pragma unroll
        for (int i = 0; i < 2; i++) {
            float2 fa = __half22float2(ha[i]);
            float2 fb = __half22float2(hb[i]);
            acc2[i] = ffma2(pack2(fa.x, fa.y), wa2, acc2[i]);
            acc2[i] = ffma2(pack2(fb.x, fb.y), wb2, acc2[i]);
        }
    }
    if (j < dg) {
        int2 e = eid[p0 + j];
        float w = leaky_exp(as_[(size_t)e.y * 4 + h] + adh);
        den += w;
        if ((lane & 7) == 0) ex2[(size_t)e.x * 4 + h] = w;
        uint2 v = xl2[(size_t)e.y * 32 + lane];
        ull ww = pack2(w, w);
        const __half2* hp = (const __half2*)&v;
#pragma unroll
        for (int i = 0; i < 2; i++) {
            float2 f = __half22float2(hp[i]);
            acc2[i] = ffma2(pack2(f.x, f.y), ww, acc2[i]);
        }
    }
    if ((lane & 7) == 0) den2[(size_t)n * 4 + h] = den;
    float acc[4];
    unpack2(acc2[0], acc[0], acc[1]);
    unpack2(acc2[1], acc[2], acc[3]);
    float dh = 1.f / (den + 1e-16f);
#pragma unroll
    for (int i = 0; i < 4; i++) {
        acc[i] *= dh;
        acc[i] += __shfl_xor_sync(0xffffffffu, acc[i], 8);
        acc[i] += __shfl_xor_sync(0xffffffffu, acc[i], 16);
    }
    if (lane < 8) {
        const float* bp = bias + 4 * lane;
        float4 o;
        o.x = 0.25f * acc[0] + bp[0]; o.y = 0.25f * acc[1] + bp[1];
        o.z = 0.25f * acc[2] + bp[2]; o.w = 0.25f * acc[3] + bp[3];
        *(float4*)(out + (size_t)n * 32 + 4 * lane) = o;
    }
}

// ---------------- edge MLP (decomposed, fp16 P/Q, f32x2 hidden): relu(P[s]+Q[d]+alpha@B+b1) @ W2 ----------------
__launch_bounds__(256)
__global__ void edge_mlp2_kernel(const int* __restrict__ src, const int* __restrict__ dst,
                                 const __half* __restrict__ PQ,
                                 const float* __restrict__ ex2, const float* __restrict__ den2,
                                 const float* __restrict__ mW1, const float* __restrict__ mb1,
                                 const float* __restrict__ mW2, const float* __restrict__ mb2,
                                 float* __restrict__ eo) {
    __shared__ __align__(8) float W1B[4 * 64];   // rows 32..35 of mW1 (alpha part)
    __shared__ __align__(8) float B1[64];
    __shared__ ull W2p[64];         // (W2[j][0], W2[j][1]) pairs
    __shared__ float B2[2];
    int tid = threadIdx.x;
    for (int i = tid; i < 256; i += 256) W1B[i] = mW1[32 * 64 + i];
    if (tid < 64) B1[tid] = mb1[tid];
    if (tid < 128) ((float*)W2p)[tid] = mW2[tid];
    if (tid < 2) B2[tid] = mb2[tid];
    __syncthreads();

    int e = blockIdx.x * 256 + tid;
    if (e >= EE) return;
    int s = src[e], d = dst[e];

    float4 a4 = *(const float4*)(ex2 + (size_t)e * 4);
    float4 dn = *(const float4*)(den2 + (size_t)d * 4);
    ull al0_2, al1_2, al2_2, al3_2;
    {
        float al0 = a4.x / (dn.x + 1e-16f);
        float al1 = a4.y / (dn.y + 1e-16f);
        float al2 = a4.z / (dn.z + 1e-16f);
        float al3 = a4.w / (dn.w + 1e-16f);
        al0_2 = pack2(al0, al0); al1_2 = pack2(al1, al1);
        al2_2 = pack2(al2, al2); al3_2 = pack2(al3, al3);
    }

    const ull* B1p = (const ull*)B1;       // pair j2 = (B1[2j2], B1[2j2+1])
    const ull* W1Bp = (const ull*)W1B;     // row h at W1Bp[h*32 + j2]

    const uint4* PQh = (const uint4*)PQ;  // 16 uint4 per node row (128 halves)
    size_t bs = (size_t)s * 16;           // P: cols 0..63  -> uint4 idx 0..7
    size_t bd = (size_t)d * 16 + 8;       // Q: cols 64..127 -> uint4 idx 0..7

    ull o2 = pack2(B2[0], B2[1]);
#pragma unroll
    for (int qq = 0; qq < 8; qq++) {
        uint4 ph = PQh[bs + qq];
        uint4 qh = PQh[bd + qq];
        const __half2* php = (const __half2*)&ph;
        const __half2* qhp = (const __half2*)&qh;
#pragma unroll
        for (int u2 = 0; u2 < 4; u2++) {
            int j2 = qq * 4 + u2;          // hidden pair 0..31
            float2 pf = __half22float2(php[u2]);
            float2 qf = __half22float2(qhp[u2]);
            ull hv2 = add2(pack2(pf.x + qf.x, pf.y + qf.y), B1p[j2]);
            hv2 = ffma2(al0_2, W1Bp[j2], hv2);
            hv2 = ffma2(al1_2, W1Bp[32 + j2], hv2);
            hv2 = ffma2(al2_2, W1Bp[64 + j2], hv2);
            hv2 = ffma2(al3_2, W1Bp[96 + j2], hv2);
            float h0, h1;
            unpack2(hv2, h0, h1);
            h0 = fmaxf(h0, 0.f); h1 = fmaxf(h1, 0.f);
            o2 = ffma2(pack2(h0, h0), W2p[2 * j2], o2);
            o2 = ffma2(pack2(h1, h1), W2p[2 * j2 + 1], o2);
        }
    }
    float o0, o1;
    unpack2(o2, o0, o1);
    ((float2*)eo)[e] = make_float2(o0, o1);
}

// ---------------- launch ----------------
extern "C" void kernel_launch(void* const* d_in, const int* in_sizes, int n_in,
                              void* d_out, int out_size) {
    const float* x    = (const float*)d_in[0];
    const int*   ei   = (const int*)d_in[1];
    const float* W1   = (const float*)d_in[4];
    const float* a1s  = (const float*)d_in[5];
    const float* a1d  = (const float*)d_in[6];
    const float* b1   = (const float*)d_in[7];
    const float* W3   = (const float*)d_in[8];
    const float* a3s  = (const float*)d_in[9];
    const float* a3d  = (const float*)d_in[10];
    const float* b3   = (const float*)d_in[11];
    const float* mW1  = (const float*)d_in[12];
    const float* mb1  = (const float*)d_in[13];
    const float* mW2  = (const float*)d_in[14];
    const float* mb2  = (const float*)d_in[15];

    const int* src = ei;
    const int* dst = ei + EE;

    float* out_nodes = (float*)d_out;             // N*32
    float* out_edges = (float*)d_out + NN * 32;   // E*2

    __half *p_xh, *p_xl1h, *p_xl2h, *p_pqh;
    __half2 *p_w1h;
    float *p_x2, *p_a1s, *p_a1d, *p_a2s, *p_a2d, *p_ex2;
    float *p_den2, *p_wpq;
    int *p_deg, *p_ptr, *p_pos, *p_bsum;
    int2 *p_eid;
    cudaGetSymbolAddress((void**)&p_xh, g_xh);
    cudaGetSymbolAddress((void**)&p_w1h, g_w1h);
    cudaGetSymbolAddress((void**)&p_xl1h, g_xl1h);
    cudaGetSymbolAddress((void**)&p_xl2h, g_xl2h);
    cudaGetSymbolAddress((void**)&p_x2,  g_x2);
    cudaGetSymbolAddress((void**)&p_a1s, g_a1s);
    cudaGetSymbolAddress((void**)&p_a1d, g_a1d);
    cudaGetSymbolAddress((void**)&p_a2s, g_a2s);
    cudaGetSymbolAddress((void**)&p_a2d, g_a2d);
    cudaGetSymbolAddress((void**)&p_ex2, g_ex2);
    cudaGetSymbolAddress((void**)&p_den2, g_den2);
    cudaGetSymbolAddress((void**)&p_pqh, g_pqh);
    cudaGetSymbolAddress((void**)&p_wpq, g_wpq);
    cudaGetSymbolAddress((void**)&p_deg, g_deg);
    cudaGetSymbolAddress((void**)&p_ptr, g_ptr);
    cudaGetSymbolAddress((void**)&p_pos, g_pos);
    cudaGetSymbolAddress((void**)&p_bsum, g_bsum);
    cudaGetSymbolAddress((void**)&p_eid, g_eid);

    static cudaStream_t s2 = nullptr;
    static cudaEvent_t evFork = nullptr, evJoin = nullptr;
    if (!s2) {
        cudaStreamCreateWithFlags(&s2, cudaStreamNonBlocking);
        cudaEventCreateWithFlags(&evFork, cudaEventDisableTiming);
        cudaEventCreateWithFlags(&evJoin, cudaEventDisableTiming);
    }

    const int NB = (NN + 511) / 512;  // 98
    const int SMEM1 = (8704 + 16896 + 512) * 4;  // 104448 B

    cudaMemsetAsync(p_deg, 0, (size_t)NN * 4);
    cudaEventRecord(evFork, 0);                       // fork point
    cudaStreamWaitEvent(s2, evFork, 0);

    // side stream: preconvert operands, then gemm1 fp16-mma + repack
    conv_x<<<(NN * 16 + 255) / 256, 256, 0, s2>>>(x, p_xh);
    conv_w1<<<(64 * 64 + 255) / 256, 256, 0, s2>>>(W1, p_w1h);

    // main stream: CSR build chain
    hist_kernel<<<(EE + 255) / 256, 256>>>(dst, p_deg);

    cudaFuncSetAttribute((const void*)gemm1_f16,
                         cudaFuncAttributeMaxDynamicSharedMemorySize, SMEM1);
    gemm1_f16<<<(NN + 127) / 128, 256, SMEM1, s2>>>(
        p_xh, p_w1h, p_xl1h, a1s, a1d, p_a1s, p_a1d, NN);
    repack_wpq<<<(32 * 128 + 255) / 256, 256, 0, s2>>>(mW1, p_wpq);
    cudaEventRecord(evJoin, s2);

    scanA_kernel<<<NB, 512>>>(p_deg, p_ptr, p_bsum);
    scanB_kernel<<<1, 128>>>(p_bsum, NB);
    scanC_kernel<<<NB, 512>>>(p_ptr, p_bsum, p_pos);
    scatter_kernel<<<(EE + 255) / 256, 256>>>(src, dst, p_pos, p_eid);

    cudaStreamWaitEvent(0, evJoin, 0);                // join

    // Layer 1 aggregation (fused exp/den/finalize)
    agg_csr64<<<(NN + 7) / 8, 256>>>(p_eid, p_ptr, p_deg, p_xl1h,
                                     p_a1s, p_a1d, b1, p_x2);

    // Layer 2
    cudaFuncSetAttribute((const void*)gemm_xw<64, 128, 128, 256, 8, true, true>,
                         cudaFuncAttributeMaxDynamicSharedMemorySize, 65536);
    gemm_xw<64, 128, 128, 256, 8, true, true><<<(NN + 127) / 128, 256, 65536>>>(
        p_x2, W3, p_xl2h, a3s, a3d, p_a2s, p_a2d, NN);
    agg_csr32<<<(NN + 7) / 8, 256>>>(p_eid, p_ptr, p_deg, p_xl2h,
                                     p_a2s, p_a2d, b3, out_nodes,
                                     p_ex2, p_den2);

    // Edge MLP: per-node P/Q precompute (fp16 out), then light per-edge kernel
    cudaFuncSetAttribute((const void*)gemm_xw<32, 128, 128, 256, 8, true, false>,
                         cudaFuncAttributeMaxDynamicSharedMemorySize, 32768);
    gemm_xw<32, 128, 128, 256, 8, true, false><<<(NN + 127) / 128, 256, 32768>>>(
        out_nodes, p_wpq, p_pqh, nullptr, nullptr, nullptr, nullptr, NN);
    edge_mlp2_kernel<<<(EE + 255) / 256, 256>>>(src, dst, p_pqh, p_ex2, p_den2,
                                                mW1, mb1, mW2, mb2, out_edges);
}